// round 2
// baseline (speedup 1.0000x reference)
#include <cuda_runtime.h>
#include <math.h>

#define NNODES 50000
#define NPAD   50048              // 391 * 128
#define NEDGES 800000
#define ETOT   (NEDGES + NNODES)  // edges + self loops
#define BATCH  128
#define DIM    128
#define NEG_SLOPE 0.2f

// ---------------- scratch (device globals) ----------------------------------
__device__ float g_hA[NPAD * DIM];
__device__ float g_hB[NPAD * DIM];
__device__ float g_xl[(size_t)NPAD * 2 * DIM];
__device__ float g_asrc[NPAD * 2];
__device__ float g_adst[NPAD * 2];
__device__ int   g_deg[NNODES];
__device__ int   g_rowptr[NNODES + 1];
__device__ int   g_wp[NNODES];
__device__ int   g_col[ETOT];
__device__ float g_ew[(size_t)ETOT * 2];
__device__ int   g_bptr[BATCH + 1];
__device__ float g_qstar[BATCH * 2 * DIM];
__device__ float g_lq[BATCH * DIM];
__device__ float g_lc[BATCH * DIM];
__device__ float g_e[NNODES];
__device__ float g_w[NNODES];
__device__ float g_sm[BATCH];
__device__ float g_sinv[BATCH];

// ---------------- helpers ---------------------------------------------------
__device__ __forceinline__ float wred_sum(float v) {
#pragma unroll
    for (int o = 16; o > 0; o >>= 1) v += __shfl_xor_sync(0xffffffffu, v, o);
    return v;
}
__device__ __forceinline__ float wred_max(float v) {
#pragma unroll
    for (int o = 16; o > 0; o >>= 1) v = fmaxf(v, __shfl_xor_sync(0xffffffffu, v, o));
    return v;
}
__device__ __forceinline__ float lrelu(float v) { return v > 0.f ? v : NEG_SLOPE * v; }

// ---------------- input padding: h0 = pad(x, 128) ---------------------------
__global__ void k_init_h(const float* __restrict__ x) {
    int i = blockIdx.x * blockDim.x + threadIdx.x;  // float4 index
    if (i >= NPAD * (DIM / 4)) return;
    int n = i >> 5;
    int c = (i & 31) * 4;
    float4 v = make_float4(0.f, 0.f, 0.f, 0.f);
    if (n < NNODES) {
        if (c + 0 < 9) v.x = x[n * 9 + c + 0];
        if (c + 1 < 9) v.y = x[n * 9 + c + 1];
        if (c + 2 < 9) v.z = x[n * 9 + c + 2];
        if (c + 3 < 9) v.w = x[n * 9 + c + 3];
    }
    reinterpret_cast<float4*>(g_hA)[i] = v;
}

// ---------------- CSR build --------------------------------------------------
__global__ void k_deginit() {
    int i = blockIdx.x * blockDim.x + threadIdx.x;
    if (i < NNODES) g_deg[i] = 1;  // self loop
}
__global__ void k_hist(const int* __restrict__ dst) {
    int e = blockIdx.x * blockDim.x + threadIdx.x;
    if (e < NEDGES) atomicAdd(&g_deg[dst[e]], 1);
}
__global__ void __launch_bounds__(1024) k_scan() {
    __shared__ int ss[1024];
    int tid = threadIdx.x;
    const int per = (NNODES + 1023) / 1024;
    int st = tid * per;
    int en = min(st + per, NNODES);
    int s = 0;
    for (int i = st; i < en; i++) s += g_deg[i];
    ss[tid] = s;
    __syncthreads();
    for (int off = 1; off < 1024; off <<= 1) {
        int v = (tid >= off) ? ss[tid - off] : 0;
        __syncthreads();
        ss[tid] += v;
        __syncthreads();
    }
    int run = (tid == 0) ? 0 : ss[tid - 1];
    for (int i = st; i < en; i++) {
        g_rowptr[i] = run;
        g_wp[i] = run;
        run += g_deg[i];
    }
    if (tid == 1023) g_rowptr[NNODES] = ss[1023];
}
__global__ void k_scatter(const int* __restrict__ src, const int* __restrict__ dst) {
    int i = blockIdx.x * blockDim.x + threadIdx.x;
    if (i < NEDGES) {
        int d = dst[i];
        int p = atomicAdd(&g_wp[d], 1);
        g_col[p] = src[i];
    } else if (i < ETOT) {
        int n = i - NEDGES;
        int p = atomicAdd(&g_wp[n], 1);
        g_col[p] = n;
    }
}
__global__ void k_bptr(const int* __restrict__ batch) {
    int b = threadIdx.x;
    if (b > BATCH) return;
    if (b == BATCH) { g_bptr[BATCH] = NNODES; return; }
    int lo = 0, hi = NNODES;
    while (lo < hi) {
        int mid = (lo + hi) >> 1;
        if (batch[mid] < b) lo = mid + 1; else hi = mid;
    }
    g_bptr[b] = lo;
}

// ---------------- SGEMM: xl[NPAD,256] = h[NPAD,128] @ W[128,256] -------------
__global__ void __launch_bounds__(256) k_sgemm(const float* __restrict__ A,
                                               const float* __restrict__ W, int keff) {
    __shared__ float As[8][128];
    __shared__ float Bs[8][128];
    const int tid = threadIdx.x;
    const int bm = blockIdx.x * 128;
    const int bn = blockIdx.y * 128;
    const int aRow = tid >> 1, aCol = (tid & 1) * 4;
    const int bRow = tid >> 5, bCol = (tid & 31) * 4;
    const int tx = tid & 15, ty = tid >> 4;
    float acc[8][8];
#pragma unroll
    for (int i = 0; i < 8; i++)
#pragma unroll
        for (int j = 0; j < 8; j++) acc[i][j] = 0.f;

    for (int k0 = 0; k0 < keff; k0 += 8) {
        float4 a = *reinterpret_cast<const float4*>(A + (size_t)(bm + aRow) * DIM + k0 + aCol);
        As[aCol + 0][aRow] = a.x;
        As[aCol + 1][aRow] = a.y;
        As[aCol + 2][aRow] = a.z;
        As[aCol + 3][aRow] = a.w;
        float4 b = *reinterpret_cast<const float4*>(W + (size_t)(k0 + bRow) * 256 + bn + bCol);
        *reinterpret_cast<float4*>(&Bs[bRow][bCol]) = b;
        __syncthreads();
#pragma unroll
        for (int k = 0; k < 8; k++) {
            float ra[8], rb[8];
            *reinterpret_cast<float4*>(&ra[0]) = *reinterpret_cast<const float4*>(&As[k][ty * 4]);
            *reinterpret_cast<float4*>(&ra[4]) = *reinterpret_cast<const float4*>(&As[k][64 + ty * 4]);
            *reinterpret_cast<float4*>(&rb[0]) = *reinterpret_cast<const float4*>(&Bs[k][tx * 4]);
            *reinterpret_cast<float4*>(&rb[4]) = *reinterpret_cast<const float4*>(&Bs[k][64 + tx * 4]);
#pragma unroll
            for (int i = 0; i < 8; i++)
#pragma unroll
                for (int j = 0; j < 8; j++) acc[i][j] += ra[i] * rb[j];
        }
        __syncthreads();
    }
#pragma unroll
    for (int i = 0; i < 8; i++) {
        int r = bm + ((i < 4) ? ty * 4 + i : 64 + ty * 4 + i - 4);
        float4 v0 = make_float4(acc[i][0], acc[i][1], acc[i][2], acc[i][3]);
        float4 v1 = make_float4(acc[i][4], acc[i][5], acc[i][6], acc[i][7]);
        *reinterpret_cast<float4*>(g_xl + (size_t)r * 256 + bn + tx * 4) = v0;
        *reinterpret_cast<float4*>(g_xl + (size_t)r * 256 + bn + 64 + tx * 4) = v1;
    }
}

// ---------------- attention scalars per node --------------------------------
__global__ void k_att(const float* __restrict__ att_src, const float* __restrict__ att_dst) {
    int gw = (blockIdx.x * blockDim.x + threadIdx.x) >> 5;
    int lane = threadIdx.x & 31;
    if (gw >= NNODES) return;
    const float4* row = reinterpret_cast<const float4*>(g_xl + (size_t)gw * 256);
    float4 v0 = row[lane], v1 = row[32 + lane];
    float4 s0 = reinterpret_cast<const float4*>(att_src)[lane];
    float4 s1 = reinterpret_cast<const float4*>(att_src)[32 + lane];
    float4 d0 = reinterpret_cast<const float4*>(att_dst)[lane];
    float4 d1 = reinterpret_cast<const float4*>(att_dst)[32 + lane];
    float rs0 = v0.x * s0.x + v0.y * s0.y + v0.z * s0.z + v0.w * s0.w;
    float rs1 = v1.x * s1.x + v1.y * s1.y + v1.z * s1.z + v1.w * s1.w;
    float rd0 = v0.x * d0.x + v0.y * d0.y + v0.z * d0.z + v0.w * d0.w;
    float rd1 = v1.x * d1.x + v1.y * d1.y + v1.z * d1.z + v1.w * d1.w;
    rs0 = wred_sum(rs0); rs1 = wred_sum(rs1);
    rd0 = wred_sum(rd0); rd1 = wred_sum(rd1);
    if (lane == 0) {
        g_asrc[gw * 2] = rs0; g_asrc[gw * 2 + 1] = rs1;
        g_adst[gw * 2] = rd0; g_adst[gw * 2 + 1] = rd1;
    }
}

// ---------------- softmax-aggregate (warp per dst node) ----------------------
__global__ void k_aggregate(const float* __restrict__ bias, float* __restrict__ out) {
    int gw = (blockIdx.x * blockDim.x + threadIdx.x) >> 5;
    int lane = threadIdx.x & 31;
    if (gw >= NNODES) return;
    int p0 = g_rowptr[gw], p1 = g_rowptr[gw + 1];
    float ad0 = g_adst[gw * 2], ad1 = g_adst[gw * 2 + 1];

    // pass 1: max logit per head
    float m0 = -1e30f, m1 = -1e30f;
    for (int p = p0 + lane; p < p1; p += 32) {
        int s = g_col[p];
        float l0 = lrelu(g_asrc[s * 2] + ad0);
        float l1 = lrelu(g_asrc[s * 2 + 1] + ad1);
        m0 = fmaxf(m0, l0); m1 = fmaxf(m1, l1);
    }
    m0 = wred_max(m0); m1 = wred_max(m1);

    // pass 2: exp weights + sums
    float s0 = 0.f, s1 = 0.f;
    for (int p = p0 + lane; p < p1; p += 32) {
        int s = g_col[p];
        float l0 = lrelu(g_asrc[s * 2] + ad0);
        float l1 = lrelu(g_asrc[s * 2 + 1] + ad1);
        float e0 = __expf(l0 - m0), e1 = __expf(l1 - m1);
        g_ew[(size_t)p * 2] = e0; g_ew[(size_t)p * 2 + 1] = e1;
        s0 += e0; s1 += e1;
    }
    s0 = wred_sum(s0); s1 = wred_sum(s1);
    float i0 = 1.f / (s0 + 1e-16f), i1 = 1.f / (s1 + 1e-16f);

    // pass 3: weighted gather of xl rows
    float4 a0 = make_float4(0.f, 0.f, 0.f, 0.f);
    float4 a1 = make_float4(0.f, 0.f, 0.f, 0.f);
    for (int p = p0; p < p1; ++p) {
        int s = g_col[p];
        float2 w = *reinterpret_cast<const float2*>(&g_ew[(size_t)p * 2]);
        const float4* row = reinterpret_cast<const float4*>(g_xl + (size_t)s * 256);
        float4 v0 = row[lane], v1 = row[32 + lane];
        a0.x += w.x * v0.x; a0.y += w.x * v0.y; a0.z += w.x * v0.z; a0.w += w.x * v0.w;
        a1.x += w.y * v1.x; a1.y += w.y * v1.y; a1.z += w.y * v1.z; a1.w += w.y * v1.w;
    }
    float4 bv = reinterpret_cast<const float4*>(bias)[lane];
    float4 o;
    o.x = 0.5f * (a0.x * i0 + a1.x * i1) + bv.x;
    o.y = 0.5f * (a0.y * i0 + a1.y * i1) + bv.y;
    o.z = 0.5f * (a0.z * i0 + a1.z * i1) + bv.z;
    o.w = 0.5f * (a0.w * i0 + a1.w * i1) + bv.w;
    *reinterpret_cast<float4*>(out + (size_t)gw * DIM + lane * 4) = o;
}

// ---------------- Set2Set ----------------------------------------------------
__global__ void k_zero_s2s() {
    int i = blockIdx.x * blockDim.x + threadIdx.x;
    if (i < BATCH * 256) g_qstar[i] = 0.f;
    else if (i < BATCH * 256 + BATCH * 128) g_lq[i - BATCH * 256] = 0.f;
    else if (i < BATCH * 256 + 2 * BATCH * 128) g_lc[i - BATCH * 256 - BATCH * 128] = 0.f;
}

__global__ void __launch_bounds__(512) k_lstm(const float* __restrict__ Wih,
                                              const float* __restrict__ Whh,
                                              const float* __restrict__ bih,
                                              const float* __restrict__ bhh) {
    int b = blockIdx.x;
    int tid = threadIdx.x;
    __shared__ float qs[256];
    __shared__ float hs[128];
    __shared__ float gates[512];
    if (tid < 256) qs[tid] = g_qstar[b * 256 + tid];
    else if (tid < 384) hs[tid - 256] = g_lq[b * 128 + (tid - 256)];
    __syncthreads();
    float acc = bih[tid] + bhh[tid];
    const float4* wi = reinterpret_cast<const float4*>(Wih + (size_t)tid * 256);
#pragma unroll 8
    for (int k = 0; k < 64; k++) {
        float4 w = wi[k];
        acc += w.x * qs[k * 4] + w.y * qs[k * 4 + 1] + w.z * qs[k * 4 + 2] + w.w * qs[k * 4 + 3];
    }
    const float4* wh = reinterpret_cast<const float4*>(Whh + (size_t)tid * 128);
#pragma unroll 8
    for (int k = 0; k < 32; k++) {
        float4 w = wh[k];
        acc += w.x * hs[k * 4] + w.y * hs[k * 4 + 1] + w.z * hs[k * 4 + 2] + w.w * hs[k * 4 + 3];
    }
    gates[tid] = acc;
    __syncthreads();
    if (tid < 128) {
        float gi = 1.f / (1.f + __expf(-gates[tid]));
        float gf = 1.f / (1.f + __expf(-gates[128 + tid]));
        float gg = tanhf(gates[256 + tid]);
        float go = 1.f / (1.f + __expf(-gates[384 + tid]));
        float c2 = gf * g_lc[b * 128 + tid] + gi * gg;
        float q = go * tanhf(c2);
        g_lc[b * 128 + tid] = c2;
        g_lq[b * 128 + tid] = q;
        g_qstar[b * 256 + tid] = q;
    }
}

__global__ void k_e(const float* __restrict__ h, const int* __restrict__ batch) {
    int gw = (blockIdx.x * blockDim.x + threadIdx.x) >> 5;
    int lane = threadIdx.x & 31;
    if (gw >= NNODES) return;
    int b = batch[gw];
    float4 hv = reinterpret_cast<const float4*>(h + (size_t)gw * DIM)[lane];
    float4 qv = reinterpret_cast<const float4*>(g_lq + (size_t)b * DIM)[lane];
    float r = hv.x * qv.x + hv.y * qv.y + hv.z * qv.z + hv.w * qv.w;
    r = wred_sum(r);
    if (lane == 0) g_e[gw] = r;
}

__global__ void __launch_bounds__(256) k_segstat() {
    int b = blockIdx.x;
    int tid = threadIdx.x;
    int p0 = g_bptr[b], p1 = g_bptr[b + 1];
    __shared__ float red[256];
    float m = -1e30f;
    for (int n = p0 + tid; n < p1; n += 256) m = fmaxf(m, g_e[n]);
    red[tid] = m;
    __syncthreads();
    for (int off = 128; off > 0; off >>= 1) {
        if (tid < off) red[tid] = fmaxf(red[tid], red[tid + off]);
        __syncthreads();
    }
    m = red[0];
    __syncthreads();
    float s = 0.f;
    for (int n = p0 + tid; n < p1; n += 256) s += __expf(g_e[n] - m);
    red[tid] = s;
    __syncthreads();
    for (int off = 128; off > 0; off >>= 1) {
        if (tid < off) red[tid] += red[tid + off];
        __syncthreads();
    }
    if (tid == 0) {
        g_sm[b] = m;
        g_sinv[b] = 1.f / (red[0] + 1e-16f);
    }
}

__global__ void k_wk(const int* __restrict__ batch) {
    int i = blockIdx.x * blockDim.x + threadIdx.x;
    if (i >= NNODES) return;
    int b = batch[i];
    g_w[i] = __expf(g_e[i] - g_sm[b]) * g_sinv[b];
}

__global__ void __launch_bounds__(128) k_r(const float* __restrict__ h) {
    int b = blockIdx.x;
    int d = threadIdx.x;
    int p0 = g_bptr[b], p1 = g_bptr[b + 1];
    float acc = 0.f;
    for (int n = p0; n < p1; n++) acc += g_w[n] * h[(size_t)n * DIM + d];
    g_qstar[b * 256 + 128 + d] = acc;
}

// ---------------- final MLP --------------------------------------------------
__global__ void __launch_bounds__(128) k_mlp(const float* __restrict__ W1, const float* __restrict__ b1,
                                             const float* __restrict__ W2, const float* __restrict__ b2,
                                             float* __restrict__ out) {
    int b = blockIdx.x;
    int j = threadIdx.x;
    __shared__ float qs[256];
    __shared__ float hid[128];
    qs[j] = g_qstar[b * 256 + j];
    qs[128 + j] = g_qstar[b * 256 + 128 + j];
    __syncthreads();
    float acc = b1[j];
#pragma unroll 8
    for (int k = 0; k < 256; k++) acc += qs[k] * W1[k * 128 + j];
    hid[j] = fmaxf(acc, 0.f);
    __syncthreads();
    float acc2 = b2[j];
#pragma unroll 8
    for (int k = 0; k < 128; k++) acc2 += hid[k] * W2[k * 128 + j];
    out[b * 128 + j] = acc2;
}

// ---------------- launch -----------------------------------------------------
extern "C" void kernel_launch(void* const* d_in, const int* in_sizes, int n_in,
                              void* d_out, int out_size) {
    const float* x        = (const float*)d_in[0];
    const int*   ei       = (const int*)d_in[1];     // int64 inputs delivered as int32
    const int*   batch    = (const int*)d_in[3];
    const float* gat_W    = (const float*)d_in[4];
    const float* att_src  = (const float*)d_in[5];
    const float* att_dst  = (const float*)d_in[6];
    const float* gat_bias = (const float*)d_in[7];
    const float* Wih      = (const float*)d_in[8];
    const float* Whh      = (const float*)d_in[9];
    const float* bih      = (const float*)d_in[10];
    const float* bhh      = (const float*)d_in[11];
    const float* W1       = (const float*)d_in[12];
    const float* b1       = (const float*)d_in[13];
    const float* W2       = (const float*)d_in[14];
    const float* b2       = (const float*)d_in[15];
    float*       out      = (float*)d_out;

    const int* src = ei;
    const int* dst = ei + NEDGES;

    float* hA = nullptr;
    float* hB = nullptr;
    cudaGetSymbolAddress((void**)&hA, g_hA);
    cudaGetSymbolAddress((void**)&hB, g_hB);

    const int warpBlocks = (NNODES * 32 + 255) / 256;

    k_init_h<<<(NPAD * (DIM / 4) + 255) / 256, 256>>>(x);
    k_deginit<<<(NNODES + 255) / 256, 256>>>();
    k_hist<<<(NEDGES + 255) / 256, 256>>>(dst);
    k_scan<<<1, 1024>>>();
    k_scatter<<<(ETOT + 255) / 256, 256>>>(src, dst);
    k_bptr<<<1, 256>>>(batch);
    k_zero_s2s<<<(BATCH * 512 + 255) / 256, 256>>>();

    float* cur = hA;
    float* nxt = hB;
    for (int c = 0; c < 3; c++) {
        dim3 g(NPAD / 128, 2);
        k_sgemm<<<g, 256>>>(cur, gat_W, (c == 0) ? 16 : 128);
        k_att<<<warpBlocks, 256>>>(att_src, att_dst);
        k_aggregate<<<warpBlocks, 256>>>(gat_bias, nxt);
        float* t = cur; cur = nxt; nxt = t;
    }

    for (int s = 0; s < 3; s++) {
        k_lstm<<<BATCH, 512>>>(Wih, Whh, bih, bhh);
        k_e<<<warpBlocks, 256>>>(cur, batch);
        k_segstat<<<BATCH, 256>>>();
        k_wk<<<(NNODES + 255) / 256, 256>>>(batch);
        k_r<<<BATCH, 128>>>(cur);
    }

    k_mlp<<<BATCH, 128>>>(W1, b1, W2, b2, out);
}

// round 3
// speedup vs baseline: 1.3203x; 1.3203x over previous
#include <cuda_runtime.h>
#include <math.h>

#define NNODES 50000
#define NPAD   50048              // 391 * 128
#define NEDGES 800000
#define ETOT   (NEDGES + NNODES)  // edges + self loops
#define BATCH  128
#define DIM    128
#define NEG_SLOPE 0.2f
#define NCHUNK 196                // ceil(50000/256)
#define RCH    8                  // k_r chunks per segment

// ---------------- scratch (device globals) ----------------------------------
__device__ float g_hA[NPAD * DIM];
__device__ float g_hB[NPAD * DIM];
__device__ float g_xl[(size_t)NPAD * 2 * DIM];
__device__ float g_asrc[NPAD * 2];
__device__ float g_adst[NPAD * 2];
__device__ int   g_deg[NNODES];
__device__ int   g_rowptr[NNODES + 1];
__device__ int   g_wp[NNODES];
__device__ int   g_col[ETOT];
__device__ float g_ew[(size_t)ETOT * 2];
__device__ int   g_bsum[256];
__device__ int   g_bbase[256];
__device__ int   g_bptr[BATCH + 1];
__device__ float g_qstar[BATCH * 2 * DIM];
__device__ float g_lq[BATCH * DIM];
__device__ float g_lc[BATCH * DIM];
__device__ float g_e[NNODES];
__device__ float g_w[NNODES];
__device__ float g_sm[BATCH];
__device__ float g_sinv[BATCH];
__device__ float g_rpart[BATCH * RCH * DIM];

// ---------------- helpers ---------------------------------------------------
__device__ __forceinline__ float wred_sum(float v) {
#pragma unroll
    for (int o = 16; o > 0; o >>= 1) v += __shfl_xor_sync(0xffffffffu, v, o);
    return v;
}
__device__ __forceinline__ float wred_max(float v) {
#pragma unroll
    for (int o = 16; o > 0; o >>= 1) v = fmaxf(v, __shfl_xor_sync(0xffffffffu, v, o));
    return v;
}
__device__ __forceinline__ float lrelu(float v) { return v > 0.f ? v : NEG_SLOPE * v; }

// ---------------- input padding: h0 = pad(x, 128) ---------------------------
__global__ void k_init_h(const float* __restrict__ x) {
    int i = blockIdx.x * blockDim.x + threadIdx.x;  // float4 index
    if (i >= NPAD * (DIM / 4)) return;
    int n = i >> 5;
    int c = (i & 31) * 4;
    float4 v = make_float4(0.f, 0.f, 0.f, 0.f);
    if (n < NNODES) {
        if (c + 0 < 9) v.x = x[n * 9 + c + 0];
        if (c + 1 < 9) v.y = x[n * 9 + c + 1];
        if (c + 2 < 9) v.z = x[n * 9 + c + 2];
        if (c + 3 < 9) v.w = x[n * 9 + c + 3];
    }
    reinterpret_cast<float4*>(g_hA)[i] = v;
}

// ---------------- CSR build --------------------------------------------------
__global__ void k_deginit() {
    int i = blockIdx.x * blockDim.x + threadIdx.x;
    if (i < NNODES) g_deg[i] = 1;  // self loop
}
__global__ void k_hist(const int* __restrict__ dst) {
    int e = blockIdx.x * blockDim.x + threadIdx.x;
    if (e < NEDGES) atomicAdd(&g_deg[dst[e]], 1);
}
// phase 1: per-chunk sums (256 nodes per block)
__global__ void __launch_bounds__(256) k_scan1() {
    __shared__ int ss[256];
    int t = threadIdx.x;
    int idx = blockIdx.x * 256 + t;
    ss[t] = (idx < NNODES) ? g_deg[idx] : 0;
    __syncthreads();
    for (int off = 128; off > 0; off >>= 1) {
        if (t < off) ss[t] += ss[t + off];
        __syncthreads();
    }
    if (t == 0) g_bsum[blockIdx.x] = ss[0];
}
// phase 2: scan chunk sums (single small block)
__global__ void __launch_bounds__(256) k_scan2() {
    __shared__ int ss[256];
    int t = threadIdx.x;
    int v = (t < NCHUNK) ? g_bsum[t] : 0;
    ss[t] = v;
    __syncthreads();
    for (int off = 1; off < 256; off <<= 1) {
        int x = (t >= off) ? ss[t - off] : 0;
        __syncthreads();
        ss[t] += x;
        __syncthreads();
    }
    if (t < NCHUNK) g_bbase[t] = ss[t] - v;  // exclusive
}
// phase 3: per-chunk exclusive scan + base
__global__ void __launch_bounds__(256) k_scan3() {
    __shared__ int ss[256];
    int t = threadIdx.x;
    int idx = blockIdx.x * 256 + t;
    int v = (idx < NNODES) ? g_deg[idx] : 0;
    ss[t] = v;
    __syncthreads();
    for (int off = 1; off < 256; off <<= 1) {
        int x = (t >= off) ? ss[t - off] : 0;
        __syncthreads();
        ss[t] += x;
        __syncthreads();
    }
    if (idx < NNODES) {
        int r = g_bbase[blockIdx.x] + ss[t] - v;
        g_rowptr[idx] = r;
        g_wp[idx] = r;
    }
    if (idx == 0) g_rowptr[NNODES] = ETOT;
}
__global__ void k_scatter(const int* __restrict__ src, const int* __restrict__ dst) {
    int i = blockIdx.x * blockDim.x + threadIdx.x;
    if (i < NEDGES) {
        int d = dst[i];
        int p = atomicAdd(&g_wp[d], 1);
        g_col[p] = src[i];
    } else if (i < ETOT) {
        int n = i - NEDGES;
        int p = atomicAdd(&g_wp[n], 1);
        g_col[p] = n;
    }
}
__global__ void k_bptr(const int* __restrict__ batch) {
    int b = threadIdx.x;
    if (b > BATCH) return;
    if (b == BATCH) { g_bptr[BATCH] = NNODES; return; }
    int lo = 0, hi = NNODES;
    while (lo < hi) {
        int mid = (lo + hi) >> 1;
        if (batch[mid] < b) lo = mid + 1; else hi = mid;
    }
    g_bptr[b] = lo;
}

// ---------------- SGEMM: xl[NPAD,256] = h[NPAD,128] @ W[128,256] -------------
__global__ void __launch_bounds__(256) k_sgemm(const float* __restrict__ A,
                                               const float* __restrict__ W, int keff) {
    __shared__ float As[8][128];
    __shared__ float Bs[8][128];
    const int tid = threadIdx.x;
    const int bm = blockIdx.x * 128;
    const int bn = blockIdx.y * 128;
    const int aRow = tid >> 1, aCol = (tid & 1) * 4;
    const int bRow = tid >> 5, bCol = (tid & 31) * 4;
    const int tx = tid & 15, ty = tid >> 4;
    float acc[8][8];
#pragma unroll
    for (int i = 0; i < 8; i++)
#pragma unroll
        for (int j = 0; j < 8; j++) acc[i][j] = 0.f;

    for (int k0 = 0; k0 < keff; k0 += 8) {
        float4 a = *reinterpret_cast<const float4*>(A + (size_t)(bm + aRow) * DIM + k0 + aCol);
        As[aCol + 0][aRow] = a.x;
        As[aCol + 1][aRow] = a.y;
        As[aCol + 2][aRow] = a.z;
        As[aCol + 3][aRow] = a.w;
        float4 b = *reinterpret_cast<const float4*>(W + (size_t)(k0 + bRow) * 256 + bn + bCol);
        *reinterpret_cast<float4*>(&Bs[bRow][bCol]) = b;
        __syncthreads();
#pragma unroll
        for (int k = 0; k < 8; k++) {
            float ra[8], rb[8];
            *reinterpret_cast<float4*>(&ra[0]) = *reinterpret_cast<const float4*>(&As[k][ty * 4]);
            *reinterpret_cast<float4*>(&ra[4]) = *reinterpret_cast<const float4*>(&As[k][64 + ty * 4]);
            *reinterpret_cast<float4*>(&rb[0]) = *reinterpret_cast<const float4*>(&Bs[k][tx * 4]);
            *reinterpret_cast<float4*>(&rb[4]) = *reinterpret_cast<const float4*>(&Bs[k][64 + tx * 4]);
#pragma unroll
            for (int i = 0; i < 8; i++)
#pragma unroll
                for (int j = 0; j < 8; j++) acc[i][j] += ra[i] * rb[j];
        }
        __syncthreads();
    }
#pragma unroll
    for (int i = 0; i < 8; i++) {
        int r = bm + ((i < 4) ? ty * 4 + i : 64 + ty * 4 + i - 4);
        float4 v0 = make_float4(acc[i][0], acc[i][1], acc[i][2], acc[i][3]);
        float4 v1 = make_float4(acc[i][4], acc[i][5], acc[i][6], acc[i][7]);
        *reinterpret_cast<float4*>(g_xl + (size_t)r * 256 + bn + tx * 4) = v0;
        *reinterpret_cast<float4*>(g_xl + (size_t)r * 256 + bn + 64 + tx * 4) = v1;
    }
}

// ---------------- attention scalars per node --------------------------------
__global__ void k_att(const float* __restrict__ att_src, const float* __restrict__ att_dst) {
    int gw = (blockIdx.x * blockDim.x + threadIdx.x) >> 5;
    int lane = threadIdx.x & 31;
    if (gw >= NNODES) return;
    const float4* row = reinterpret_cast<const float4*>(g_xl + (size_t)gw * 256);
    float4 v0 = row[lane], v1 = row[32 + lane];
    float4 s0 = reinterpret_cast<const float4*>(att_src)[lane];
    float4 s1 = reinterpret_cast<const float4*>(att_src)[32 + lane];
    float4 d0 = reinterpret_cast<const float4*>(att_dst)[lane];
    float4 d1 = reinterpret_cast<const float4*>(att_dst)[32 + lane];
    float rs0 = v0.x * s0.x + v0.y * s0.y + v0.z * s0.z + v0.w * s0.w;
    float rs1 = v1.x * s1.x + v1.y * s1.y + v1.z * s1.z + v1.w * s1.w;
    float rd0 = v0.x * d0.x + v0.y * d0.y + v0.z * d0.z + v0.w * d0.w;
    float rd1 = v1.x * d1.x + v1.y * d1.y + v1.z * d1.z + v1.w * d1.w;
    rs0 = wred_sum(rs0); rs1 = wred_sum(rs1);
    rd0 = wred_sum(rd0); rd1 = wred_sum(rd1);
    if (lane == 0) {
        g_asrc[gw * 2] = rs0; g_asrc[gw * 2 + 1] = rs1;
        g_adst[gw * 2] = rd0; g_adst[gw * 2 + 1] = rd1;
    }
}

// ---------------- softmax-aggregate (warp per dst node) ----------------------
__global__ void k_aggregate(const float* __restrict__ bias, float* __restrict__ out) {
    int gw = (blockIdx.x * blockDim.x + threadIdx.x) >> 5;
    int lane = threadIdx.x & 31;
    if (gw >= NNODES) return;
    int p0 = g_rowptr[gw], p1 = g_rowptr[gw + 1];
    float ad0 = g_adst[gw * 2], ad1 = g_adst[gw * 2 + 1];

    // pass 1: gather logits once (random loads), store sequential, track max
    float m0 = -1e30f, m1 = -1e30f;
    for (int p = p0 + lane; p < p1; p += 32) {
        int s = g_col[p];
        float2 as = *reinterpret_cast<const float2*>(&g_asrc[s * 2]);
        float l0 = lrelu(as.x + ad0);
        float l1 = lrelu(as.y + ad1);
        g_ew[(size_t)p * 2] = l0; g_ew[(size_t)p * 2 + 1] = l1;
        m0 = fmaxf(m0, l0); m1 = fmaxf(m1, l1);
    }
    m0 = wred_max(m0); m1 = wred_max(m1);

    // pass 2: streamed exp + sums
    float s0 = 0.f, s1 = 0.f;
    for (int p = p0 + lane; p < p1; p += 32) {
        float2 l = *reinterpret_cast<const float2*>(&g_ew[(size_t)p * 2]);
        float e0 = __expf(l.x - m0), e1 = __expf(l.y - m1);
        g_ew[(size_t)p * 2] = e0; g_ew[(size_t)p * 2 + 1] = e1;
        s0 += e0; s1 += e1;
    }
    s0 = wred_sum(s0); s1 = wred_sum(s1);
    float i0 = 1.f / (s0 + 1e-16f), i1 = 1.f / (s1 + 1e-16f);

    // pass 3: weighted gather of xl rows (1-deep pipeline on col/weight)
    float4 a0 = make_float4(0.f, 0.f, 0.f, 0.f);
    float4 a1 = make_float4(0.f, 0.f, 0.f, 0.f);
    int sN = g_col[p0];
    float2 wN = *reinterpret_cast<const float2*>(&g_ew[(size_t)p0 * 2]);
    for (int p = p0; p < p1; ++p) {
        int s = sN;
        float2 w = wN;
        if (p + 1 < p1) {
            sN = g_col[p + 1];
            wN = *reinterpret_cast<const float2*>(&g_ew[(size_t)(p + 1) * 2]);
        }
        const float4* row = reinterpret_cast<const float4*>(g_xl + (size_t)s * 256);
        float4 v0 = row[lane], v1 = row[32 + lane];
        a0.x += w.x * v0.x; a0.y += w.x * v0.y; a0.z += w.x * v0.z; a0.w += w.x * v0.w;
        a1.x += w.y * v1.x; a1.y += w.y * v1.y; a1.z += w.y * v1.z; a1.w += w.y * v1.w;
    }
    float4 bv = reinterpret_cast<const float4*>(bias)[lane];
    float4 o;
    o.x = 0.5f * (a0.x * i0 + a1.x * i1) + bv.x;
    o.y = 0.5f * (a0.y * i0 + a1.y * i1) + bv.y;
    o.z = 0.5f * (a0.z * i0 + a1.z * i1) + bv.z;
    o.w = 0.5f * (a0.w * i0 + a1.w * i1) + bv.w;
    *reinterpret_cast<float4*>(out + (size_t)gw * DIM + lane * 4) = o;
}

// ---------------- Set2Set ----------------------------------------------------
__global__ void k_zero_s2s() {
    int i = blockIdx.x * blockDim.x + threadIdx.x;
    if (i < BATCH * 256) g_qstar[i] = 0.f;
    else if (i < BATCH * 256 + BATCH * 128) g_lq[i - BATCH * 256] = 0.f;
    else if (i < BATCH * 256 + 2 * BATCH * 128) g_lc[i - BATCH * 256 - BATCH * 128] = 0.f;
}

__global__ void __launch_bounds__(512) k_lstm(const float* __restrict__ Wih,
                                              const float* __restrict__ Whh,
                                              const float* __restrict__ bih,
                                              const float* __restrict__ bhh) {
    int b = blockIdx.x;
    int tid = threadIdx.x;
    __shared__ float qs[256];
    __shared__ float hs[128];
    __shared__ float gates[512];
    if (tid < 256) qs[tid] = g_qstar[b * 256 + tid];
    else if (tid < 384) hs[tid - 256] = g_lq[b * 128 + (tid - 256)];
    __syncthreads();
    float acc = bih[tid] + bhh[tid];
    const float4* wi = reinterpret_cast<const float4*>(Wih + (size_t)tid * 256);
#pragma unroll 8
    for (int k = 0; k < 64; k++) {
        float4 w = wi[k];
        acc += w.x * qs[k * 4] + w.y * qs[k * 4 + 1] + w.z * qs[k * 4 + 2] + w.w * qs[k * 4 + 3];
    }
    const float4* wh = reinterpret_cast<const float4*>(Whh + (size_t)tid * 128);
#pragma unroll 8
    for (int k = 0; k < 32; k++) {
        float4 w = wh[k];
        acc += w.x * hs[k * 4] + w.y * hs[k * 4 + 1] + w.z * hs[k * 4 + 2] + w.w * hs[k * 4 + 3];
    }
    gates[tid] = acc;
    __syncthreads();
    if (tid < 128) {
        float gi = 1.f / (1.f + __expf(-gates[tid]));
        float gf = 1.f / (1.f + __expf(-gates[128 + tid]));
        float gg = tanhf(gates[256 + tid]);
        float go = 1.f / (1.f + __expf(-gates[384 + tid]));
        float c2 = gf * g_lc[b * 128 + tid] + gi * gg;
        float q = go * tanhf(c2);
        g_lc[b * 128 + tid] = c2;
        g_lq[b * 128 + tid] = q;
        g_qstar[b * 256 + tid] = q;
    }
}

__global__ void k_e(const float* __restrict__ h, const int* __restrict__ batch) {
    int gw = (blockIdx.x * blockDim.x + threadIdx.x) >> 5;
    int lane = threadIdx.x & 31;
    if (gw >= NNODES) return;
    int b = batch[gw];
    float4 hv = reinterpret_cast<const float4*>(h + (size_t)gw * DIM)[lane];
    float4 qv = reinterpret_cast<const float4*>(g_lq + (size_t)b * DIM)[lane];
    float r = hv.x * qv.x + hv.y * qv.y + hv.z * qv.z + hv.w * qv.w;
    r = wred_sum(r);
    if (lane == 0) g_e[gw] = r;
}

__global__ void __launch_bounds__(256) k_segstat() {
    int b = blockIdx.x;
    int tid = threadIdx.x;
    int p0 = g_bptr[b], p1 = g_bptr[b + 1];
    __shared__ float red[256];
    float m = -1e30f;
    for (int n = p0 + tid; n < p1; n += 256) m = fmaxf(m, g_e[n]);
    red[tid] = m;
    __syncthreads();
    for (int off = 128; off > 0; off >>= 1) {
        if (tid < off) red[tid] = fmaxf(red[tid], red[tid + off]);
        __syncthreads();
    }
    m = red[0];
    __syncthreads();
    float s = 0.f;
    for (int n = p0 + tid; n < p1; n += 256) s += __expf(g_e[n] - m);
    red[tid] = s;
    __syncthreads();
    for (int off = 128; off > 0; off >>= 1) {
        if (tid < off) red[tid] += red[tid + off];
        __syncthreads();
    }
    if (tid == 0) {
        g_sm[b] = m;
        g_sinv[b] = 1.f / (red[0] + 1e-16f);
    }
}

__global__ void k_wk(const int* __restrict__ batch) {
    int i = blockIdx.x * blockDim.x + threadIdx.x;
    if (i >= NNODES) return;
    int b = batch[i];
    g_w[i] = __expf(g_e[i] - g_sm[b]) * g_sinv[b];
}

// chunked weighted segment reduce: grid (BATCH, RCH)
__global__ void __launch_bounds__(128) k_rpart(const float* __restrict__ h) {
    int b = blockIdx.x;
    int ch = blockIdx.y;
    int d = threadIdx.x;
    int p0 = g_bptr[b], p1 = g_bptr[b + 1];
    int L = p1 - p0;
    int per = (L + RCH - 1) / RCH;
    int st = p0 + ch * per;
    int en = min(st + per, p1);
    float acc = 0.f;
    for (int n = st; n < en; n++) acc += g_w[n] * h[(size_t)n * DIM + d];
    g_rpart[((size_t)b * RCH + ch) * DIM + d] = acc;
}
__global__ void __launch_bounds__(128) k_rred() {
    int b = blockIdx.x;
    int d = threadIdx.x;
    float acc = 0.f;
#pragma unroll
    for (int ch = 0; ch < RCH; ch++) acc += g_rpart[((size_t)b * RCH + ch) * DIM + d];
    g_qstar[b * 256 + 128 + d] = acc;
}

// ---------------- final MLP --------------------------------------------------
__global__ void __launch_bounds__(128) k_mlp(const float* __restrict__ W1, const float* __restrict__ b1,
                                             const float* __restrict__ W2, const float* __restrict__ b2,
                                             float* __restrict__ out) {
    int b = blockIdx.x;
    int j = threadIdx.x;
    __shared__ float qs[256];
    __shared__ float hid[128];
    qs[j] = g_qstar[b * 256 + j];
    qs[128 + j] = g_qstar[b * 256 + 128 + j];
    __syncthreads();
    float acc = b1[j];
#pragma unroll 8
    for (int k = 0; k < 256; k++) acc += qs[k] * W1[k * 128 + j];
    hid[j] = fmaxf(acc, 0.f);
    __syncthreads();
    float acc2 = b2[j];
#pragma unroll 8
    for (int k = 0; k < 128; k++) acc2 += hid[k] * W2[k * 128 + j];
    out[b * 128 + j] = acc2;
}

// ---------------- launch -----------------------------------------------------
extern "C" void kernel_launch(void* const* d_in, const int* in_sizes, int n_in,
                              void* d_out, int out_size) {
    const float* x        = (const float*)d_in[0];
    const int*   ei       = (const int*)d_in[1];     // int64 inputs delivered as int32
    const int*   batch    = (const int*)d_in[3];
    const float* gat_W    = (const float*)d_in[4];
    const float* att_src  = (const float*)d_in[5];
    const float* att_dst  = (const float*)d_in[6];
    const float* gat_bias = (const float*)d_in[7];
    const float* Wih      = (const float*)d_in[8];
    const float* Whh      = (const float*)d_in[9];
    const float* bih      = (const float*)d_in[10];
    const float* bhh      = (const float*)d_in[11];
    const float* W1       = (const float*)d_in[12];
    const float* b1       = (const float*)d_in[13];
    const float* W2       = (const float*)d_in[14];
    const float* b2       = (const float*)d_in[15];
    float*       out      = (float*)d_out;

    const int* src = ei;
    const int* dst = ei + NEDGES;

    float* hA = nullptr;
    float* hB = nullptr;
    cudaGetSymbolAddress((void**)&hA, g_hA);
    cudaGetSymbolAddress((void**)&hB, g_hB);

    const int warpBlocks = (NNODES * 32 + 255) / 256;

    k_init_h<<<(NPAD * (DIM / 4) + 255) / 256, 256>>>(x);
    k_deginit<<<(NNODES + 255) / 256, 256>>>();
    k_hist<<<(NEDGES + 255) / 256, 256>>>(dst);
    k_scan1<<<NCHUNK, 256>>>();
    k_scan2<<<1, 256>>>();
    k_scan3<<<NCHUNK, 256>>>();
    k_scatter<<<(ETOT + 255) / 256, 256>>>(src, dst);
    k_bptr<<<1, 256>>>(batch);
    k_zero_s2s<<<(BATCH * 512 + 255) / 256, 256>>>();

    float* cur = hA;
    float* nxt = hB;
    for (int c = 0; c < 3; c++) {
        dim3 g(NPAD / 128, 2);
        k_sgemm<<<g, 256>>>(cur, gat_W, (c == 0) ? 16 : 128);
        k_att<<<warpBlocks, 256>>>(att_src, att_dst);
        k_aggregate<<<warpBlocks, 256>>>(gat_bias, nxt);
        float* t = cur; cur = nxt; nxt = t;
    }

    for (int s = 0; s < 3; s++) {
        k_lstm<<<BATCH, 512>>>(Wih, Whh, bih, bhh);
        k_e<<<warpBlocks, 256>>>(cur, batch);
        k_segstat<<<BATCH, 256>>>();
        k_wk<<<(NNODES + 255) / 256, 256>>>(batch);
        dim3 rg(BATCH, RCH);
        k_rpart<<<rg, 128>>>(cur);
        k_rred<<<BATCH, 128>>>();
    }

    k_mlp<<<BATCH, 128>>>(W1, b1, W2, b2, out);
}

// round 4
// speedup vs baseline: 1.3483x; 1.0212x over previous
#include <cuda_runtime.h>
#include <cuda_bf16.h>
#include <math.h>

#define NNODES 50000
#define NPAD   50048              // 391 * 128
#define NEDGES 800000
#define ETOT   (NEDGES + NNODES)  // edges + self loops
#define BATCH  128
#define DIM    128
#define NEG_SLOPE 0.2f
#define NCHUNK 196                // ceil(50000/256)
#define RCH    8                  // k_r chunks per segment

// ---------------- scratch (device globals) ----------------------------------
__device__ float g_hA[NPAD * DIM];
__device__ float g_hB[NPAD * DIM];
__device__ float g_xl[(size_t)NPAD * 2 * DIM];
__device__ __nv_bfloat16 g_xlh[(size_t)NPAD * 2 * DIM];
__device__ float g_asrc[NPAD * 2];
__device__ float g_adst[NPAD * 2];
__device__ int   g_deg[NNODES];
__device__ int   g_rowptr[NNODES + 1];
__device__ int   g_wp[NNODES];
__device__ int   g_col[ETOT];
__device__ float g_ew[(size_t)ETOT * 2];
__device__ int   g_bsum[256];
__device__ int   g_bbase[256];
__device__ int   g_bptr[BATCH + 1];
__device__ float g_qstar[BATCH * 2 * DIM];
__device__ float g_lq[BATCH * DIM];
__device__ float g_lc[BATCH * DIM];
__device__ float g_e[NNODES];
__device__ float g_w[NNODES];
__device__ float g_sm[BATCH];
__device__ float g_sinv[BATCH];
__device__ float g_rpart[BATCH * RCH * DIM];

// ---------------- helpers ---------------------------------------------------
__device__ __forceinline__ float wred_sum(float v) {
#pragma unroll
    for (int o = 16; o > 0; o >>= 1) v += __shfl_xor_sync(0xffffffffu, v, o);
    return v;
}
__device__ __forceinline__ float lrelu(float v) { return v > 0.f ? v : NEG_SLOPE * v; }

// ---------------- input padding: h0 = pad(x, 128) ---------------------------
__global__ void k_init_h(const float* __restrict__ x) {
    int i = blockIdx.x * blockDim.x + threadIdx.x;  // float4 index
    if (i >= NPAD * (DIM / 4)) return;
    int n = i >> 5;
    int c = (i & 31) * 4;
    float4 v = make_float4(0.f, 0.f, 0.f, 0.f);
    if (n < NNODES) {
        if (c + 0 < 9) v.x = x[n * 9 + c + 0];
        if (c + 1 < 9) v.y = x[n * 9 + c + 1];
        if (c + 2 < 9) v.z = x[n * 9 + c + 2];
        if (c + 3 < 9) v.w = x[n * 9 + c + 3];
    }
    reinterpret_cast<float4*>(g_hA)[i] = v;
}

// ---------------- CSR build --------------------------------------------------
__global__ void k_deginit() {
    int i = blockIdx.x * blockDim.x + threadIdx.x;
    if (i < NNODES) g_deg[i] = 1;  // self loop
}
__global__ void k_hist(const int* __restrict__ dst) {
    int e = blockIdx.x * blockDim.x + threadIdx.x;
    if (e < NEDGES) atomicAdd(&g_deg[dst[e]], 1);
}
__global__ void __launch_bounds__(256) k_scan1() {
    __shared__ int ss[256];
    int t = threadIdx.x;
    int idx = blockIdx.x * 256 + t;
    ss[t] = (idx < NNODES) ? g_deg[idx] : 0;
    __syncthreads();
    for (int off = 128; off > 0; off >>= 1) {
        if (t < off) ss[t] += ss[t + off];
        __syncthreads();
    }
    if (t == 0) g_bsum[blockIdx.x] = ss[0];
}
__global__ void __launch_bounds__(256) k_scan2() {
    __shared__ int ss[256];
    int t = threadIdx.x;
    int v = (t < NCHUNK) ? g_bsum[t] : 0;
    ss[t] = v;
    __syncthreads();
    for (int off = 1; off < 256; off <<= 1) {
        int x = (t >= off) ? ss[t - off] : 0;
        __syncthreads();
        ss[t] += x;
        __syncthreads();
    }
    if (t < NCHUNK) g_bbase[t] = ss[t] - v;  // exclusive
}
__global__ void __launch_bounds__(256) k_scan3() {
    __shared__ int ss[256];
    int t = threadIdx.x;
    int idx = blockIdx.x * 256 + t;
    int v = (idx < NNODES) ? g_deg[idx] : 0;
    ss[t] = v;
    __syncthreads();
    for (int off = 1; off < 256; off <<= 1) {
        int x = (t >= off) ? ss[t - off] : 0;
        __syncthreads();
        ss[t] += x;
        __syncthreads();
    }
    if (idx < NNODES) {
        int r = g_bbase[blockIdx.x] + ss[t] - v;
        g_rowptr[idx] = r;
        g_wp[idx] = r;
    }
    if (idx == 0) g_rowptr[NNODES] = ETOT;
}
__global__ void k_scatter(const int* __restrict__ src, const int* __restrict__ dst) {
    int i = blockIdx.x * blockDim.x + threadIdx.x;
    if (i < NEDGES) {
        int d = dst[i];
        int p = atomicAdd(&g_wp[d], 1);
        g_col[p] = src[i];
    } else if (i < ETOT) {
        int n = i - NEDGES;
        int p = atomicAdd(&g_wp[n], 1);
        g_col[p] = n;
    }
}
__global__ void k_bptr(const int* __restrict__ batch) {
    int b = threadIdx.x;
    if (b > BATCH) return;
    if (b == BATCH) { g_bptr[BATCH] = NNODES; return; }
    int lo = 0, hi = NNODES;
    while (lo < hi) {
        int mid = (lo + hi) >> 1;
        if (batch[mid] < b) lo = mid + 1; else hi = mid;
    }
    g_bptr[b] = lo;
}

// ---- SGEMM (double-buffered): xl = h @ W;  writes fp32 + bf16 copies --------
__global__ void __launch_bounds__(256) k_sgemm(const float* __restrict__ A,
                                               const float* __restrict__ W, int keff) {
    __shared__ float As[2][8][128];
    __shared__ float Bs[2][8][128];
    const int tid = threadIdx.x;
    const int bm = blockIdx.x * 128;
    const int bn = blockIdx.y * 128;
    const int aRow = tid >> 1, aCol = (tid & 1) * 4;
    const int bRow = tid >> 5, bCol = (tid & 31) * 4;
    const int tx = tid & 15, ty = tid >> 4;
    float acc[8][8];
#pragma unroll
    for (int i = 0; i < 8; i++)
#pragma unroll
        for (int j = 0; j < 8; j++) acc[i][j] = 0.f;

    const int nk = keff / 8;
    float4 a = *reinterpret_cast<const float4*>(A + (size_t)(bm + aRow) * DIM + aCol);
    float4 b = *reinterpret_cast<const float4*>(W + (size_t)bRow * 256 + bn + bCol);
    As[0][aCol + 0][aRow] = a.x; As[0][aCol + 1][aRow] = a.y;
    As[0][aCol + 2][aRow] = a.z; As[0][aCol + 3][aRow] = a.w;
    *reinterpret_cast<float4*>(&Bs[0][bRow][bCol]) = b;
    __syncthreads();

    for (int t = 0; t < nk; t++) {
        int cur = t & 1;
        if (t + 1 < nk) {
            int k0 = (t + 1) * 8;
            a = *reinterpret_cast<const float4*>(A + (size_t)(bm + aRow) * DIM + k0 + aCol);
            b = *reinterpret_cast<const float4*>(W + (size_t)(k0 + bRow) * 256 + bn + bCol);
        }
#pragma unroll
        for (int k = 0; k < 8; k++) {
            float ra[8], rb[8];
            *reinterpret_cast<float4*>(&ra[0]) = *reinterpret_cast<const float4*>(&As[cur][k][ty * 4]);
            *reinterpret_cast<float4*>(&ra[4]) = *reinterpret_cast<const float4*>(&As[cur][k][64 + ty * 4]);
            *reinterpret_cast<float4*>(&rb[0]) = *reinterpret_cast<const float4*>(&Bs[cur][k][tx * 4]);
            *reinterpret_cast<float4*>(&rb[4]) = *reinterpret_cast<const float4*>(&Bs[cur][k][64 + tx * 4]);
#pragma unroll
            for (int i = 0; i < 8; i++)
#pragma unroll
                for (int j = 0; j < 8; j++) acc[i][j] += ra[i] * rb[j];
        }
        if (t + 1 < nk) {
            int nb = (t + 1) & 1;
            As[nb][aCol + 0][aRow] = a.x; As[nb][aCol + 1][aRow] = a.y;
            As[nb][aCol + 2][aRow] = a.z; As[nb][aCol + 3][aRow] = a.w;
            *reinterpret_cast<float4*>(&Bs[nb][bRow][bCol]) = b;
        }
        __syncthreads();
    }
#pragma unroll
    for (int i = 0; i < 8; i++) {
        int r = bm + ((i < 4) ? ty * 4 + i : 64 + ty * 4 + i - 4);
        float4 v0 = make_float4(acc[i][0], acc[i][1], acc[i][2], acc[i][3]);
        float4 v1 = make_float4(acc[i][4], acc[i][5], acc[i][6], acc[i][7]);
        *reinterpret_cast<float4*>(g_xl + (size_t)r * 256 + bn + tx * 4) = v0;
        *reinterpret_cast<float4*>(g_xl + (size_t)r * 256 + bn + 64 + tx * 4) = v1;
        __nv_bfloat162 h0 = __floats2bfloat162_rn(v0.x, v0.y);
        __nv_bfloat162 h1 = __floats2bfloat162_rn(v0.z, v0.w);
        __nv_bfloat162 h2 = __floats2bfloat162_rn(v1.x, v1.y);
        __nv_bfloat162 h3 = __floats2bfloat162_rn(v1.z, v1.w);
        uint2 u0, u1;
        u0.x = *reinterpret_cast<unsigned*>(&h0); u0.y = *reinterpret_cast<unsigned*>(&h1);
        u1.x = *reinterpret_cast<unsigned*>(&h2); u1.y = *reinterpret_cast<unsigned*>(&h3);
        *reinterpret_cast<uint2*>(g_xlh + (size_t)r * 256 + bn + tx * 4) = u0;
        *reinterpret_cast<uint2*>(g_xlh + (size_t)r * 256 + bn + 64 + tx * 4) = u1;
    }
}

// ---------------- attention scalars per node --------------------------------
__global__ void k_att(const float* __restrict__ att_src, const float* __restrict__ att_dst) {
    int gw = (blockIdx.x * blockDim.x + threadIdx.x) >> 5;
    int lane = threadIdx.x & 31;
    if (gw >= NNODES) return;
    const float4* row = reinterpret_cast<const float4*>(g_xl + (size_t)gw * 256);
    float4 v0 = row[lane], v1 = row[32 + lane];
    float4 s0 = reinterpret_cast<const float4*>(att_src)[lane];
    float4 s1 = reinterpret_cast<const float4*>(att_src)[32 + lane];
    float4 d0 = reinterpret_cast<const float4*>(att_dst)[lane];
    float4 d1 = reinterpret_cast<const float4*>(att_dst)[32 + lane];
    float rs0 = v0.x * s0.x + v0.y * s0.y + v0.z * s0.z + v0.w * s0.w;
    float rs1 = v1.x * s1.x + v1.y * s1.y + v1.z * s1.z + v1.w * s1.w;
    float rd0 = v0.x * d0.x + v0.y * d0.y + v0.z * d0.z + v0.w * d0.w;
    float rd1 = v1.x * d1.x + v1.y * d1.y + v1.z * d1.z + v1.w * d1.w;
    rs0 = wred_sum(rs0); rs1 = wred_sum(rs1);
    rd0 = wred_sum(rd0); rd1 = wred_sum(rd1);
    if (lane == 0) {
        g_asrc[gw * 2] = rs0; g_asrc[gw * 2 + 1] = rs1;
        g_adst[gw * 2] = rd0; g_adst[gw * 2 + 1] = rd1;
    }
}

// ---------------- softmax-aggregate (warp per dst node) ----------------------
// Logits are O(1): exp() without max-subtraction is safe and mathematically
// identical after normalization -> single pass for weights+sums.
__global__ void k_aggregate(const float* __restrict__ bias, float* __restrict__ out) {
    int gw = (blockIdx.x * blockDim.x + threadIdx.x) >> 5;
    int lane = threadIdx.x & 31;
    if (gw >= NNODES) return;
    int p0 = g_rowptr[gw], p1 = g_rowptr[gw + 1];
    float ad0 = g_adst[gw * 2], ad1 = g_adst[gw * 2 + 1];

    // pass A: gather logits, exp, store weight, accumulate sums
    float s0 = 0.f, s1 = 0.f;
    for (int p = p0 + lane; p < p1; p += 32) {
        int s = g_col[p];
        float2 as = *reinterpret_cast<const float2*>(&g_asrc[s * 2]);
        float e0 = __expf(lrelu(as.x + ad0));
        float e1 = __expf(lrelu(as.y + ad1));
        g_ew[(size_t)p * 2] = e0; g_ew[(size_t)p * 2 + 1] = e1;
        s0 += e0; s1 += e1;
    }
    s0 = wred_sum(s0); s1 = wred_sum(s1);
    float i0 = 1.f / (s0 + 1e-16f), i1 = 1.f / (s1 + 1e-16f);

    // pass B: weighted bf16 gather (1-deep pipeline on col/weight)
    float4 a0 = make_float4(0.f, 0.f, 0.f, 0.f);
    float4 a1 = make_float4(0.f, 0.f, 0.f, 0.f);
    int sN = g_col[p0];
    float2 wN = *reinterpret_cast<const float2*>(&g_ew[(size_t)p0 * 2]);
    for (int p = p0; p < p1; ++p) {
        int s = sN;
        float2 w = wN;
        if (p + 1 < p1) {
            sN = g_col[p + 1];
            wN = *reinterpret_cast<const float2*>(&g_ew[(size_t)(p + 1) * 2]);
        }
        const uint2* row = reinterpret_cast<const uint2*>(g_xlh + (size_t)s * 256);
        uint2 u0 = row[lane], u1 = row[32 + lane];
        float2 f0 = __bfloat1622float2(*reinterpret_cast<__nv_bfloat162*>(&u0.x));
        float2 f1 = __bfloat1622float2(*reinterpret_cast<__nv_bfloat162*>(&u0.y));
        float2 f2 = __bfloat1622float2(*reinterpret_cast<__nv_bfloat162*>(&u1.x));
        float2 f3 = __bfloat1622float2(*reinterpret_cast<__nv_bfloat162*>(&u1.y));
        a0.x += w.x * f0.x; a0.y += w.x * f0.y; a0.z += w.x * f1.x; a0.w += w.x * f1.y;
        a1.x += w.y * f2.x; a1.y += w.y * f2.y; a1.z += w.y * f3.x; a1.w += w.y * f3.y;
    }
    float4 bv = reinterpret_cast<const float4*>(bias)[lane];
    float4 o;
    o.x = 0.5f * (a0.x * i0 + a1.x * i1) + bv.x;
    o.y = 0.5f * (a0.y * i0 + a1.y * i1) + bv.y;
    o.z = 0.5f * (a0.z * i0 + a1.z * i1) + bv.z;
    o.w = 0.5f * (a0.w * i0 + a1.w * i1) + bv.w;
    *reinterpret_cast<float4*>(out + (size_t)gw * DIM + lane * 4) = o;
}

// ---------------- Set2Set ----------------------------------------------------
__global__ void k_zero_s2s() {
    int i = blockIdx.x * blockDim.x + threadIdx.x;
    if (i < BATCH * 256) g_qstar[i] = 0.f;
    else if (i < BATCH * 256 + BATCH * 128) g_lq[i - BATCH * 256] = 0.f;
    else if (i < BATCH * 256 + 2 * BATCH * 128) g_lc[i - BATCH * 256 - BATCH * 128] = 0.f;
}

__global__ void __launch_bounds__(512) k_lstm(const float* __restrict__ Wih,
                                              const float* __restrict__ Whh,
                                              const float* __restrict__ bih,
                                              const float* __restrict__ bhh) {
    int b = blockIdx.x;
    int tid = threadIdx.x;
    __shared__ float qs[256];
    __shared__ float hs[128];
    __shared__ float gates[512];
    if (tid < 256) qs[tid] = g_qstar[b * 256 + tid];
    else if (tid < 384) hs[tid - 256] = g_lq[b * 128 + (tid - 256)];
    __syncthreads();
    float acc = bih[tid] + bhh[tid];
    const float4* wi = reinterpret_cast<const float4*>(Wih + (size_t)tid * 256);
#pragma unroll 8
    for (int k = 0; k < 64; k++) {
        float4 w = wi[k];
        acc += w.x * qs[k * 4] + w.y * qs[k * 4 + 1] + w.z * qs[k * 4 + 2] + w.w * qs[k * 4 + 3];
    }
    const float4* wh = reinterpret_cast<const float4*>(Whh + (size_t)tid * 128);
#pragma unroll 8
    for (int k = 0; k < 32; k++) {
        float4 w = wh[k];
        acc += w.x * hs[k * 4] + w.y * hs[k * 4 + 1] + w.z * hs[k * 4 + 2] + w.w * hs[k * 4 + 3];
    }
    gates[tid] = acc;
    __syncthreads();
    if (tid < 128) {
        float gi = 1.f / (1.f + __expf(-gates[tid]));
        float gf = 1.f / (1.f + __expf(-gates[128 + tid]));
        float gg = tanhf(gates[256 + tid]);
        float go = 1.f / (1.f + __expf(-gates[384 + tid]));
        float c2 = gf * g_lc[b * 128 + tid] + gi * gg;
        float q = go * tanhf(c2);
        g_lc[b * 128 + tid] = c2;
        g_lq[b * 128 + tid] = q;
        g_qstar[b * 256 + tid] = q;
    }
}

__global__ void k_e(const float* __restrict__ h, const int* __restrict__ batch) {
    int gw = (blockIdx.x * blockDim.x + threadIdx.x) >> 5;
    int lane = threadIdx.x & 31;
    if (gw >= NNODES) return;
    int b = batch[gw];
    float4 hv = reinterpret_cast<const float4*>(h + (size_t)gw * DIM)[lane];
    float4 qv = reinterpret_cast<const float4*>(g_lq + (size_t)b * DIM)[lane];
    float r = hv.x * qv.x + hv.y * qv.y + hv.z * qv.z + hv.w * qv.w;
    r = wred_sum(r);
    if (lane == 0) g_e[gw] = r;
}

__global__ void __launch_bounds__(256) k_segstat() {
    int b = blockIdx.x;
    int tid = threadIdx.x;
    int p0 = g_bptr[b], p1 = g_bptr[b + 1];
    __shared__ float red[256];
    float m = -1e30f;
    for (int n = p0 + tid; n < p1; n += 256) m = fmaxf(m, g_e[n]);
    red[tid] = m;
    __syncthreads();
    for (int off = 128; off > 0; off >>= 1) {
        if (tid < off) red[tid] = fmaxf(red[tid], red[tid + off]);
        __syncthreads();
    }
    m = red[0];
    __syncthreads();
    float s = 0.f;
    for (int n = p0 + tid; n < p1; n += 256) s += __expf(g_e[n] - m);
    red[tid] = s;
    __syncthreads();
    for (int off = 128; off > 0; off >>= 1) {
        if (tid < off) red[tid] += red[tid + off];
        __syncthreads();
    }
    if (tid == 0) {
        g_sm[b] = m;
        g_sinv[b] = 1.f / (red[0] + 1e-16f);
    }
}

__global__ void k_wk(const int* __restrict__ batch) {
    int i = blockIdx.x * blockDim.x + threadIdx.x;
    if (i >= NNODES) return;
    int b = batch[i];
    g_w[i] = __expf(g_e[i] - g_sm[b]) * g_sinv[b];
}

__global__ void __launch_bounds__(128) k_rpart(const float* __restrict__ h) {
    int b = blockIdx.x;
    int ch = blockIdx.y;
    int d = threadIdx.x;
    int p0 = g_bptr[b], p1 = g_bptr[b + 1];
    int L = p1 - p0;
    int per = (L + RCH - 1) / RCH;
    int st = p0 + ch * per;
    int en = min(st + per, p1);
    float acc = 0.f;
    for (int n = st; n < en; n++) acc += g_w[n] * h[(size_t)n * DIM + d];
    g_rpart[((size_t)b * RCH + ch) * DIM + d] = acc;
}
__global__ void __launch_bounds__(128) k_rred() {
    int b = blockIdx.x;
    int d = threadIdx.x;
    float acc = 0.f;
#pragma unroll
    for (int ch = 0; ch < RCH; ch++) acc += g_rpart[((size_t)b * RCH + ch) * DIM + d];
    g_qstar[b * 256 + 128 + d] = acc;
}

// ---------------- final MLP --------------------------------------------------
__global__ void __launch_bounds__(128) k_mlp(const float* __restrict__ W1, const float* __restrict__ b1,
                                             const float* __restrict__ W2, const float* __restrict__ b2,
                                             float* __restrict__ out) {
    int b = blockIdx.x;
    int j = threadIdx.x;
    __shared__ float qs[256];
    __shared__ float hid[128];
    qs[j] = g_qstar[b * 256 + j];
    qs[128 + j] = g_qstar[b * 256 + 128 + j];
    __syncthreads();
    float acc = b1[j];
#pragma unroll 8
    for (int k = 0; k < 256; k++) acc += qs[k] * W1[k * 128 + j];
    hid[j] = fmaxf(acc, 0.f);
    __syncthreads();
    float acc2 = b2[j];
#pragma unroll 8
    for (int k = 0; k < 128; k++) acc2 += hid[k] * W2[k * 128 + j];
    out[b * 128 + j] = acc2;
}

// ---------------- launch -----------------------------------------------------
extern "C" void kernel_launch(void* const* d_in, const int* in_sizes, int n_in,
                              void* d_out, int out_size) {
    const float* x        = (const float*)d_in[0];
    const int*   ei       = (const int*)d_in[1];     // int64 inputs delivered as int32
    const int*   batch    = (const int*)d_in[3];
    const float* gat_W    = (const float*)d_in[4];
    const float* att_src  = (const float*)d_in[5];
    const float* att_dst  = (const float*)d_in[6];
    const float* gat_bias = (const float*)d_in[7];
    const float* Wih      = (const float*)d_in[8];
    const float* Whh      = (const float*)d_in[9];
    const float* bih      = (const float*)d_in[10];
    const float* bhh      = (const float*)d_in[11];
    const float* W1       = (const float*)d_in[12];
    const float* b1       = (const float*)d_in[13];
    const float* W2       = (const float*)d_in[14];
    const float* b2       = (const float*)d_in[15];
    float*       out      = (float*)d_out;

    const int* src = ei;
    const int* dst = ei + NEDGES;

    float* hA = nullptr;
    float* hB = nullptr;
    cudaGetSymbolAddress((void**)&hA, g_hA);
    cudaGetSymbolAddress((void**)&hB, g_hB);

    const int warpBlocks = (NNODES * 32 + 255) / 256;

    k_init_h<<<(NPAD * (DIM / 4) + 255) / 256, 256>>>(x);
    k_deginit<<<(NNODES + 255) / 256, 256>>>();
    k_hist<<<(NEDGES + 255) / 256, 256>>>(dst);
    k_scan1<<<NCHUNK, 256>>>();
    k_scan2<<<1, 256>>>();
    k_scan3<<<NCHUNK, 256>>>();
    k_scatter<<<(ETOT + 255) / 256, 256>>>(src, dst);
    k_bptr<<<1, 256>>>(batch);
    k_zero_s2s<<<(BATCH * 512 + 255) / 256, 256>>>();

    float* cur = hA;
    float* nxt = hB;
    for (int c = 0; c < 3; c++) {
        dim3 g(NPAD / 128, 2);
        k_sgemm<<<g, 256>>>(cur, gat_W, (c == 0) ? 16 : 128);
        k_att<<<warpBlocks, 256>>>(att_src, att_dst);
        k_aggregate<<<warpBlocks, 256>>>(gat_bias, nxt);
        float* t = cur; cur = nxt; nxt = t;
    }

    for (int s = 0; s < 3; s++) {
        k_lstm<<<BATCH, 512>>>(Wih, Whh, bih, bhh);
        k_e<<<warpBlocks, 256>>>(cur, batch);
        k_segstat<<<BATCH, 256>>>();
        k_wk<<<(NNODES + 255) / 256, 256>>>(batch);
        dim3 rg(BATCH, RCH);
        k_rpart<<<rg, 128>>>(cur);
        k_rred<<<BATCH, 128>>>();
    }

    k_mlp<<<BATCH, 128>>>(W1, b1, W2, b2, out);
}

// round 5
// speedup vs baseline: 1.5204x; 1.1276x over previous
#include <cuda_runtime.h>
#include <math.h>

#define NNODES 50000
#define NPAD   50048              // 391 * 128
#define NEDGES 800000
#define ETOT   (NEDGES + NNODES)  // edges + self loops
#define BATCH  128
#define DIM    128
#define NEG_SLOPE 0.2f
#define NCHUNK 196                // ceil(50000/256)
#define RCH    8                  // k_r chunks per segment

// ---------------- scratch (device globals) ----------------------------------
__device__ float g_hA[NPAD * DIM];
__device__ float g_hB[NPAD * DIM];
__device__ float g_xl[(size_t)NPAD * 2 * DIM];
__device__ float g_asrc[NPAD * 2];
__device__ float g_adst[NPAD * 2];
__device__ int   g_deg[NNODES];
__device__ int   g_rowptr[NNODES + 1];
__device__ int   g_wp[NNODES];
__device__ int   g_col[ETOT];
__device__ float g_ew[(size_t)ETOT * 2];
__device__ int   g_bsum[256];
__device__ int   g_bbase[256];
__device__ int   g_bptr[BATCH + 1];
__device__ float g_qstar[BATCH * 2 * DIM];
__device__ float g_lq[BATCH * DIM];
__device__ float g_lc[BATCH * DIM];
__device__ float g_e[NNODES];
__device__ float g_w[NNODES];
__device__ float g_sm[BATCH];
__device__ float g_sinv[BATCH];
__device__ float g_rpart[BATCH * RCH * DIM];

// ---------------- helpers ---------------------------------------------------
__device__ __forceinline__ float wred_sum(float v) {
#pragma unroll
    for (int o = 16; o > 0; o >>= 1) v += __shfl_xor_sync(0xffffffffu, v, o);
    return v;
}
__device__ __forceinline__ float lrelu(float v) { return v > 0.f ? v : NEG_SLOPE * v; }
__device__ __forceinline__ unsigned f2tf32(float f) {
    unsigned u;
    asm("cvt.rna.tf32.f32 %0, %1;" : "=r"(u) : "f"(f));
    return u;
}

// ---------------- input padding: h0 = pad(x, 128) ---------------------------
__global__ void k_init_h(const float* __restrict__ x) {
    int i = blockIdx.x * blockDim.x + threadIdx.x;  // float4 index
    if (i >= NPAD * (DIM / 4)) return;
    int n = i >> 5;
    int c = (i & 31) * 4;
    float4 v = make_float4(0.f, 0.f, 0.f, 0.f);
    if (n < NNODES) {
        if (c + 0 < 9) v.x = x[n * 9 + c + 0];
        if (c + 1 < 9) v.y = x[n * 9 + c + 1];
        if (c + 2 < 9) v.z = x[n * 9 + c + 2];
        if (c + 3 < 9) v.w = x[n * 9 + c + 3];
    }
    reinterpret_cast<float4*>(g_hA)[i] = v;
}

// ---------------- CSR build --------------------------------------------------
__global__ void k_deginit() {
    int i = blockIdx.x * blockDim.x + threadIdx.x;
    if (i < NNODES) g_deg[i] = 1;  // self loop
}
__global__ void k_hist(const int* __restrict__ dst) {
    int e = blockIdx.x * blockDim.x + threadIdx.x;
    if (e < NEDGES) atomicAdd(&g_deg[dst[e]], 1);
}
__global__ void __launch_bounds__(256) k_scan1() {
    __shared__ int ss[256];
    int t = threadIdx.x;
    int idx = blockIdx.x * 256 + t;
    ss[t] = (idx < NNODES) ? g_deg[idx] : 0;
    __syncthreads();
    for (int off = 128; off > 0; off >>= 1) {
        if (t < off) ss[t] += ss[t + off];
        __syncthreads();
    }
    if (t == 0) g_bsum[blockIdx.x] = ss[0];
}
__global__ void __launch_bounds__(256) k_scan2() {
    __shared__ int ss[256];
    int t = threadIdx.x;
    int v = (t < NCHUNK) ? g_bsum[t] : 0;
    ss[t] = v;
    __syncthreads();
    for (int off = 1; off < 256; off <<= 1) {
        int x = (t >= off) ? ss[t - off] : 0;
        __syncthreads();
        ss[t] += x;
        __syncthreads();
    }
    if (t < NCHUNK) g_bbase[t] = ss[t] - v;  // exclusive
}
__global__ void __launch_bounds__(256) k_scan3() {
    __shared__ int ss[256];
    int t = threadIdx.x;
    int idx = blockIdx.x * 256 + t;
    int v = (idx < NNODES) ? g_deg[idx] : 0;
    ss[t] = v;
    __syncthreads();
    for (int off = 1; off < 256; off <<= 1) {
        int x = (t >= off) ? ss[t - off] : 0;
        __syncthreads();
        ss[t] += x;
        __syncthreads();
    }
    if (idx < NNODES) {
        int r = g_bbase[blockIdx.x] + ss[t] - v;
        g_rowptr[idx] = r;
        g_wp[idx] = r;
    }
    if (idx == 0) g_rowptr[NNODES] = ETOT;
}
__global__ void k_scatter(const int* __restrict__ src, const int* __restrict__ dst) {
    int i = blockIdx.x * blockDim.x + threadIdx.x;
    if (i < NEDGES) {
        int d = dst[i];
        int p = atomicAdd(&g_wp[d], 1);
        g_col[p] = src[i];
    } else if (i < ETOT) {
        int n = i - NEDGES;
        int p = atomicAdd(&g_wp[n], 1);
        g_col[p] = n;
    }
}
__global__ void k_bptr(const int* __restrict__ batch) {
    int b = threadIdx.x;
    if (b > BATCH) return;
    if (b == BATCH) { g_bptr[BATCH] = NNODES; return; }
    int lo = 0, hi = NNODES;
    while (lo < hi) {
        int mid = (lo + hi) >> 1;
        if (batch[mid] < b) lo = mid + 1; else hi = mid;
    }
    g_bptr[b] = lo;
}

// ---- tf32 MMA GEMM + fused attention dots -----------------------------------
// xl[M,256] = h[M,128] @ W[128,256]; block = (128 rows) x (one head = 128 cols)
// Also writes g_asrc/g_adst for its rows/head (full-head dot inside block).
#define AST 132
__global__ void __launch_bounds__(256) k_gemm_att(const float* __restrict__ A,
                                                  const float* __restrict__ W,
                                                  const float* __restrict__ att_src,
                                                  const float* __restrict__ att_dst) {
    __shared__ unsigned As[32][AST];   // [k][m] tf32 bits
    __shared__ unsigned Bs[32][AST];   // [k][n] tf32 bits
    __shared__ float sAs[128], sAd[128];

    const int tid = threadIdx.x;
    const int bm = blockIdx.x * 128;
    const int head = blockIdx.y;         // 0 or 1
    const int bn = head * 128;
    const int wid = tid >> 5, lane = tid & 31;
    const int wm = wid >> 2, wn = wid & 3;   // warp grid 2 x 4
    const int g = lane >> 2, tig = lane & 3;

    if (tid < 128) { sAs[tid] = 0.f; sAd[tid] = 0.f; }

    float c[4][4][4];
#pragma unroll
    for (int mt = 0; mt < 4; mt++)
#pragma unroll
        for (int nt = 0; nt < 4; nt++)
#pragma unroll
            for (int j = 0; j < 4; j++) c[mt][nt][j] = 0.f;

    for (int k0 = 0; k0 < 128; k0 += 32) {
        // A: 128 rows x 32 k  (1024 float4 slots)
#pragma unroll
        for (int i = 0; i < 4; i++) {
            int slot = tid + i * 256;
            int r = slot >> 3, kq = (slot & 7) * 4;
            float4 v = *reinterpret_cast<const float4*>(A + (size_t)(bm + r) * 128 + k0 + kq);
            As[kq + 0][r] = f2tf32(v.x);
            As[kq + 1][r] = f2tf32(v.y);
            As[kq + 2][r] = f2tf32(v.z);
            As[kq + 3][r] = f2tf32(v.w);
        }
        // B: 32 k x 128 n
#pragma unroll
        for (int i = 0; i < 4; i++) {
            int slot = tid + i * 256;
            int kk = slot >> 5, nq = (slot & 31) * 4;
            float4 v = *reinterpret_cast<const float4*>(W + (size_t)(k0 + kk) * 256 + bn + nq);
            uint4 u;
            u.x = f2tf32(v.x); u.y = f2tf32(v.y); u.z = f2tf32(v.z); u.w = f2tf32(v.w);
            *reinterpret_cast<uint4*>(&Bs[kk][nq]) = u;
        }
        __syncthreads();
#pragma unroll
        for (int ks = 0; ks < 4; ks++) {
            int kb = ks * 8;
            unsigned af[4][4], bf[4][2];
#pragma unroll
            for (int mt = 0; mt < 4; mt++) {
                int r0 = wm * 64 + mt * 16 + g;
                af[mt][0] = As[kb + tig][r0];
                af[mt][1] = As[kb + tig][r0 + 8];
                af[mt][2] = As[kb + tig + 4][r0];
                af[mt][3] = As[kb + tig + 4][r0 + 8];
            }
#pragma unroll
            for (int nt = 0; nt < 4; nt++) {
                int c0 = wn * 32 + nt * 8 + g;
                bf[nt][0] = Bs[kb + tig][c0];
                bf[nt][1] = Bs[kb + tig + 4][c0];
            }
#pragma unroll
            for (int mt = 0; mt < 4; mt++)
#pragma unroll
                for (int nt = 0; nt < 4; nt++) {
                    asm volatile(
                        "mma.sync.aligned.m16n8k8.row.col.f32.tf32.tf32.f32 "
                        "{%0,%1,%2,%3}, {%4,%5,%6,%7}, {%8,%9}, {%0,%1,%2,%3};"
                        : "+f"(c[mt][nt][0]), "+f"(c[mt][nt][1]),
                          "+f"(c[mt][nt][2]), "+f"(c[mt][nt][3])
                        : "r"(af[mt][0]), "r"(af[mt][1]), "r"(af[mt][2]), "r"(af[mt][3]),
                          "r"(bf[nt][0]), "r"(bf[nt][1]));
                }
        }
        __syncthreads();
    }

    // attention vectors for this thread's 8 columns (within head)
    float asr[8], adr[8];
#pragma unroll
    for (int nt = 0; nt < 4; nt++) {
#pragma unroll
        for (int j = 0; j < 2; j++) {
            int col = wn * 32 + nt * 8 + tig * 2 + j;
            asr[nt * 2 + j] = att_src[head * 128 + col];
            adr[nt * 2 + j] = att_dst[head * 128 + col];
        }
    }

    // store C + att partials
#pragma unroll
    for (int mt = 0; mt < 4; mt++) {
#pragma unroll
        for (int half = 0; half < 2; half++) {
            int lr = wm * 64 + mt * 16 + g + half * 8;
            int row = bm + lr;
            float ds = 0.f, dd = 0.f;
#pragma unroll
            for (int nt = 0; nt < 4; nt++) {
                float v0 = c[mt][nt][half * 2];
                float v1 = c[mt][nt][half * 2 + 1];
                int col = bn + wn * 32 + nt * 8 + tig * 2;
                *reinterpret_cast<float2*>(g_xl + (size_t)row * 256 + col) = make_float2(v0, v1);
                ds += v0 * asr[nt * 2] + v1 * asr[nt * 2 + 1];
                dd += v0 * adr[nt * 2] + v1 * adr[nt * 2 + 1];
            }
            // reduce over tig quad (lanes tig=0..3 share same row)
            ds += __shfl_xor_sync(0xffffffffu, ds, 1);
            ds += __shfl_xor_sync(0xffffffffu, ds, 2);
            dd += __shfl_xor_sync(0xffffffffu, dd, 1);
            dd += __shfl_xor_sync(0xffffffffu, dd, 2);
            if (tig == 0) {
                atomicAdd(&sAs[lr], ds);
                atomicAdd(&sAd[lr], dd);
            }
        }
    }
    __syncthreads();
    if (tid < 128) {
        g_asrc[(size_t)(bm + tid) * 2 + head] = sAs[tid];
        g_adst[(size_t)(bm + tid) * 2 + head] = sAd[tid];
    }
}

// ---------------- softmax-aggregate (warp per dst node) ----------------------
__global__ void k_aggregate(const float* __restrict__ bias, float* __restrict__ out) {
    int gw = (blockIdx.x * blockDim.x + threadIdx.x) >> 5;
    int lane = threadIdx.x & 31;
    if (gw >= NNODES) return;
    int p0 = g_rowptr[gw], p1 = g_rowptr[gw + 1];
    float ad0 = g_adst[gw * 2], ad1 = g_adst[gw * 2 + 1];

    // pass A: gather logits, exp, store weight, accumulate sums
    float s0 = 0.f, s1 = 0.f;
    for (int p = p0 + lane; p < p1; p += 32) {
        int s = g_col[p];
        float2 as = *reinterpret_cast<const float2*>(&g_asrc[s * 2]);
        float e0 = __expf(lrelu(as.x + ad0));
        float e1 = __expf(lrelu(as.y + ad1));
        g_ew[(size_t)p * 2] = e0; g_ew[(size_t)p * 2 + 1] = e1;
        s0 += e0; s1 += e1;
    }
    s0 = wred_sum(s0); s1 = wred_sum(s1);
    float i0 = 1.f / (s0 + 1e-16f), i1 = 1.f / (s1 + 1e-16f);

    // pass B: weighted fp32 gather (1-deep pipeline on col/weight)
    float4 a0 = make_float4(0.f, 0.f, 0.f, 0.f);
    float4 a1 = make_float4(0.f, 0.f, 0.f, 0.f);
    int sN = g_col[p0];
    float2 wN = *reinterpret_cast<const float2*>(&g_ew[(size_t)p0 * 2]);
    for (int p = p0; p < p1; ++p) {
        int s = sN;
        float2 w = wN;
        if (p + 1 < p1) {
            sN = g_col[p + 1];
            wN = *reinterpret_cast<const float2*>(&g_ew[(size_t)(p + 1) * 2]);
        }
        const float4* row = reinterpret_cast<const float4*>(g_xl + (size_t)s * 256);
        float4 v0 = row[lane], v1 = row[32 + lane];
        a0.x += w.x * v0.x; a0.y += w.x * v0.y; a0.z += w.x * v0.z; a0.w += w.x * v0.w;
        a1.x += w.y * v1.x; a1.y += w.y * v1.y; a1.z += w.y * v1.z; a1.w += w.y * v1.w;
    }
    float4 bv = reinterpret_cast<const float4*>(bias)[lane];
    float4 o;
    o.x = 0.5f * (a0.x * i0 + a1.x * i1) + bv.x;
    o.y = 0.5f * (a0.y * i0 + a1.y * i1) + bv.y;
    o.z = 0.5f * (a0.z * i0 + a1.z * i1) + bv.z;
    o.w = 0.5f * (a0.w * i0 + a1.w * i1) + bv.w;
    *reinterpret_cast<float4*>(out + (size_t)gw * DIM + lane * 4) = o;
}

// ---------------- Set2Set ----------------------------------------------------
__global__ void k_zero_s2s() {
    int i = blockIdx.x * blockDim.x + threadIdx.x;
    if (i < BATCH * 256) g_qstar[i] = 0.f;
    else if (i < BATCH * 256 + BATCH * 128) g_lq[i - BATCH * 256] = 0.f;
    else if (i < BATCH * 256 + 2 * BATCH * 128) g_lc[i - BATCH * 256 - BATCH * 128] = 0.f;
}

__global__ void __launch_bounds__(512) k_lstm(const float* __restrict__ Wih,
                                              const float* __restrict__ Whh,
                                              const float* __restrict__ bih,
                                              const float* __restrict__ bhh) {
    int b = blockIdx.x;
    int tid = threadIdx.x;
    __shared__ float qs[256];
    __shared__ float hs[128];
    __shared__ float gates[512];
    if (tid < 256) qs[tid] = g_qstar[b * 256 + tid];
    else if (tid < 384) hs[tid - 256] = g_lq[b * 128 + (tid - 256)];
    __syncthreads();
    float acc = bih[tid] + bhh[tid];
    const float4* wi = reinterpret_cast<const float4*>(Wih + (size_t)tid * 256);
#pragma unroll 8
    for (int k = 0; k < 64; k++) {
        float4 w = wi[k];
        acc += w.x * qs[k * 4] + w.y * qs[k * 4 + 1] + w.z * qs[k * 4 + 2] + w.w * qs[k * 4 + 3];
    }
    const float4* wh = reinterpret_cast<const float4*>(Whh + (size_t)tid * 128);
#pragma unroll 8
    for (int k = 0; k < 32; k++) {
        float4 w = wh[k];
        acc += w.x * hs[k * 4] + w.y * hs[k * 4 + 1] + w.z * hs[k * 4 + 2] + w.w * hs[k * 4 + 3];
    }
    gates[tid] = acc;
    __syncthreads();
    if (tid < 128) {
        float gi = 1.f / (1.f + __expf(-gates[tid]));
        float gf = 1.f / (1.f + __expf(-gates[128 + tid]));
        float gg = tanhf(gates[256 + tid]);
        float go = 1.f / (1.f + __expf(-gates[384 + tid]));
        float c2 = gf * g_lc[b * 128 + tid] + gi * gg;
        float q = go * tanhf(c2);
        g_lc[b * 128 + tid] = c2;
        g_lq[b * 128 + tid] = q;
        g_qstar[b * 256 + tid] = q;
    }
}

__global__ void k_e(const float* __restrict__ h, const int* __restrict__ batch) {
    int gw = (blockIdx.x * blockDim.x + threadIdx.x) >> 5;
    int lane = threadIdx.x & 31;
    if (gw >= NNODES) return;
    int b = batch[gw];
    float4 hv = reinterpret_cast<const float4*>(h + (size_t)gw * DIM)[lane];
    float4 qv = reinterpret_cast<const float4*>(g_lq + (size_t)b * DIM)[lane];
    float r = hv.x * qv.x + hv.y * qv.y + hv.z * qv.z + hv.w * qv.w;
    r = wred_sum(r);
    if (lane == 0) g_e[gw] = r;
}

__global__ void __launch_bounds__(256) k_segstat() {
    int b = blockIdx.x;
    int tid = threadIdx.x;
    int p0 = g_bptr[b], p1 = g_bptr[b + 1];
    __shared__ float red[256];
    float m = -1e30f;
    for (int n = p0 + tid; n < p1; n += 256) m = fmaxf(m, g_e[n]);
    red[tid] = m;
    __syncthreads();
    for (int off = 128; off > 0; off >>= 1) {
        if (tid < off) red[tid] = fmaxf(red[tid], red[tid + off]);
        __syncthreads();
    }
    m = red[0];
    __syncthreads();
    float s = 0.f;
    for (int n = p0 + tid; n < p1; n += 256) s += __expf(g_e[n] - m);
    red[tid] = s;
    __syncthreads();
    for (int off = 128; off > 0; off >>= 1) {
        if (tid < off) red[tid] += red[tid + off];
        __syncthreads();
    }
    if (tid == 0) {
        g_sm[b] = m;
        g_sinv[b] = 1.f / (red[0] + 1e-16f);
    }
}

__global__ void k_wk(const int* __restrict__ batch) {
    int i = blockIdx.x * blockDim.x + threadIdx.x;
    if (i >= NNODES) return;
    int b = batch[i];
    g_w[i] = __expf(g_e[i] - g_sm[b]) * g_sinv[b];
}

__global__ void __launch_bounds__(128) k_rpart(const float* __restrict__ h) {
    int b = blockIdx.x;
    int ch = blockIdx.y;
    int d = threadIdx.x;
    int p0 = g_bptr[b], p1 = g_bptr[b + 1];
    int L = p1 - p0;
    int per = (L + RCH - 1) / RCH;
    int st = p0 + ch * per;
    int en = min(st + per, p1);
    float acc = 0.f;
    for (int n = st; n < en; n++) acc += g_w[n] * h[(size_t)n * DIM + d];
    g_rpart[((size_t)b * RCH + ch) * DIM + d] = acc;
}
__global__ void __launch_bounds__(128) k_rred() {
    int b = blockIdx.x;
    int d = threadIdx.x;
    float acc = 0.f;
#pragma unroll
    for (int ch = 0; ch < RCH; ch++) acc += g_rpart[((size_t)b * RCH + ch) * DIM + d];
    g_qstar[b * 256 + 128 + d] = acc;
}

// ---------------- final MLP --------------------------------------------------
__global__ void __launch_bounds__(128) k_mlp(const float* __restrict__ W1, const float* __restrict__ b1,
                                             const float* __restrict__ W2, const float* __restrict__ b2,
                                             float* __restrict__ out) {
    int b = blockIdx.x;
    int j = threadIdx.x;
    __shared__ float qs[256];
    __shared__ float hid[128];
    qs[j] = g_qstar[b * 256 + j];
    qs[128 + j] = g_qstar[b * 256 + 128 + j];
    __syncthreads();
    float acc = b1[j];
#pragma unroll 8
    for (int k = 0; k < 256; k++) acc += qs[k] * W1[k * 128 + j];
    hid[j] = fmaxf(acc, 0.f);
    __syncthreads();
    float acc2 = b2[j];
#pragma unroll 8
    for (int k = 0; k < 128; k++) acc2 += hid[k] * W2[k * 128 + j];
    out[b * 128 + j] = acc2;
}

// ---------------- launch -----------------------------------------------------
extern "C" void kernel_launch(void* const* d_in, const int* in_sizes, int n_in,
                              void* d_out, int out_size) {
    const float* x        = (const float*)d_in[0];
    const int*   ei       = (const int*)d_in[1];     // int64 inputs delivered as int32
    const int*   batch    = (const int*)d_in[3];
    const float* gat_W    = (const float*)d_in[4];
    const float* att_src  = (const float*)d_in[5];
    const float* att_dst  = (const float*)d_in[6];
    const float* gat_bias = (const float*)d_in[7];
    const float* Wih      = (const float*)d_in[8];
    const float* Whh      = (const float*)d_in[9];
    const float* bih      = (const float*)d_in[10];
    const float* bhh      = (const float*)d_in[11];
    const float* W1       = (const float*)d_in[12];
    const float* b1       = (const float*)d_in[13];
    const float* W2       = (const float*)d_in[14];
    const float* b2       = (const float*)d_in[15];
    float*       out      = (float*)d_out;

    const int* src = ei;
    const int* dst = ei + NEDGES;

    float* hA = nullptr;
    float* hB = nullptr;
    cudaGetSymbolAddress((void**)&hA, g_hA);
    cudaGetSymbolAddress((void**)&hB, g_hB);

    const int warpBlocks = (NNODES * 32 + 255) / 256;

    k_init_h<<<(NPAD * (DIM / 4) + 255) / 256, 256>>>(x);
    k_deginit<<<(NNODES + 255) / 256, 256>>>();
    k_hist<<<(NEDGES + 255) / 256, 256>>>(dst);
    k_scan1<<<NCHUNK, 256>>>();
    k_scan2<<<1, 256>>>();
    k_scan3<<<NCHUNK, 256>>>();
    k_scatter<<<(ETOT + 255) / 256, 256>>>(src, dst);
    k_bptr<<<1, 256>>>(batch);
    k_zero_s2s<<<(BATCH * 512 + 255) / 256, 256>>>();

    float* cur = hA;
    float* nxt = hB;
    for (int c = 0; c < 3; c++) {
        dim3 g(NPAD / 128, 2);
        k_gemm_att<<<g, 256>>>(cur, gat_W, att_src, att_dst);
        k_aggregate<<<warpBlocks, 256>>>(gat_bias, nxt);
        float* t = cur; cur = nxt; nxt = t;
    }

    for (int s = 0; s < 3; s++) {
        k_lstm<<<BATCH, 512>>>(Wih, Whh, bih, bhh);
        k_e<<<warpBlocks, 256>>>(cur, batch);
        k_segstat<<<BATCH, 256>>>();
        k_wk<<<(NNODES + 255) / 256, 256>>>(batch);
        dim3 rg(BATCH, RCH);
        k_rpart<<<rg, 128>>>(cur);
        k_rred<<<BATCH, 128>>>();
    }

    k_mlp<<<BATCH, 128>>>(W1, b1, W2, b2, out);
}

// round 6
// speedup vs baseline: 1.5480x; 1.0182x over previous
#include <cuda_runtime.h>
#include <math.h>

#define NNODES 50000
#define NPAD   50048              // 391 * 128
#define NEDGES 800000
#define ETOT   (NEDGES + NNODES)  // edges + self loops
#define BATCH  128
#define DIM    128
#define NEG_SLOPE 0.2f
#define NCHUNK 196                // ceil(50000/256)
#define RCH    8                  // k_r chunks per segment
#define CAP    128                // smem weight stash per warp

// ---------------- scratch (device globals) ----------------------------------
__device__ float    g_hA[NPAD * DIM];
__device__ float    g_hB[NPAD * DIM];
__device__ unsigned g_hT[NPAD * DIM];          // tf32 copy of current h
__device__ unsigned g_WT[DIM * 2 * DIM];       // tf32 copy of gat_W
__device__ float    g_xl[(size_t)NPAD * 2 * DIM];
__device__ float    g_asrc[NPAD * 2];
__device__ float    g_adst[NPAD * 2];
__device__ int      g_deg[NNODES];
__device__ int      g_rowptr[NNODES + 1];
__device__ int      g_wp[NNODES];
__device__ int      g_col[ETOT];
__device__ float    g_ew[(size_t)2 * ETOT];    // [head][edge] fallback
__device__ int      g_bsum[256];
__device__ int      g_bbase[256];
__device__ int      g_bptr[BATCH + 1];
__device__ float    g_qstar[BATCH * 2 * DIM];
__device__ float    g_lq[BATCH * DIM];
__device__ float    g_lc[BATCH * DIM];
__device__ float    g_e[NNODES];
__device__ float    g_sm[BATCH];
__device__ float    g_sinv[BATCH];
__device__ float    g_rpart[BATCH * RCH * DIM];

// ---------------- helpers ---------------------------------------------------
__device__ __forceinline__ float wred_sum(float v) {
#pragma unroll
    for (int o = 16; o > 0; o >>= 1) v += __shfl_xor_sync(0xffffffffu, v, o);
    return v;
}
__device__ __forceinline__ float lrelu(float v) { return v > 0.f ? v : NEG_SLOPE * v; }
__device__ __forceinline__ unsigned f2tf32(float f) {
    unsigned u;
    asm("cvt.rna.tf32.f32 %0, %1;" : "=r"(u) : "f"(f));
    return u;
}

// ---------------- input padding + deg init + tf32 copy ----------------------
__global__ void k_init_h(const float* __restrict__ x) {
    int i = blockIdx.x * blockDim.x + threadIdx.x;  // float4 index
    if (i >= NPAD * (DIM / 4)) return;
    int n = i >> 5;
    int c = (i & 31) * 4;
    float4 v = make_float4(0.f, 0.f, 0.f, 0.f);
    if (n < NNODES) {
        if (c + 0 < 9) v.x = x[n * 9 + c + 0];
        if (c + 1 < 9) v.y = x[n * 9 + c + 1];
        if (c + 2 < 9) v.z = x[n * 9 + c + 2];
        if (c + 3 < 9) v.w = x[n * 9 + c + 3];
        if ((i & 31) == 0) g_deg[n] = 1;  // self loop
    }
    reinterpret_cast<float4*>(g_hA)[i] = v;
    uint4 u;
    u.x = f2tf32(v.x); u.y = f2tf32(v.y); u.z = f2tf32(v.z); u.w = f2tf32(v.w);
    reinterpret_cast<uint4*>(g_hT)[i] = u;
}

__global__ void k_cvtW(const float* __restrict__ W) {
    int i = blockIdx.x * blockDim.x + threadIdx.x;
    if (i < DIM * 2 * DIM) g_WT[i] = f2tf32(W[i]);
}

// ---------------- CSR build --------------------------------------------------
__global__ void k_hist(const int* __restrict__ dst) {
    int e = blockIdx.x * blockDim.x + threadIdx.x;
    if (e < NEDGES) atomicAdd(&g_deg[dst[e]], 1);
}
__global__ void __launch_bounds__(256) k_scan1() {
    __shared__ int ss[256];
    int t = threadIdx.x;
    int idx = blockIdx.x * 256 + t;
    ss[t] = (idx < NNODES) ? g_deg[idx] : 0;
    __syncthreads();
    for (int off = 128; off > 0; off >>= 1) {
        if (t < off) ss[t] += ss[t + off];
        __syncthreads();
    }
    if (t == 0) g_bsum[blockIdx.x] = ss[0];
}
__global__ void __launch_bounds__(256) k_scan2() {
    __shared__ int ss[256];
    int t = threadIdx.x;
    int v = (t < NCHUNK) ? g_bsum[t] : 0;
    ss[t] = v;
    __syncthreads();
    for (int off = 1; off < 256; off <<= 1) {
        int x = (t >= off) ? ss[t - off] : 0;
        __syncthreads();
        ss[t] += x;
        __syncthreads();
    }
    if (t < NCHUNK) g_bbase[t] = ss[t] - v;  // exclusive
}
__global__ void __launch_bounds__(256) k_scan3() {
    __shared__ int ss[256];
    int t = threadIdx.x;
    int idx = blockIdx.x * 256 + t;
    int v = (idx < NNODES) ? g_deg[idx] : 0;
    ss[t] = v;
    __syncthreads();
    for (int off = 1; off < 256; off <<= 1) {
        int x = (t >= off) ? ss[t - off] : 0;
        __syncthreads();
        ss[t] += x;
        __syncthreads();
    }
    if (idx < NNODES) {
        int r = g_bbase[blockIdx.x] + ss[t] - v;
        g_rowptr[idx] = r;
        g_wp[idx] = r;
    }
    if (idx == 0) g_rowptr[NNODES] = ETOT;
}
__global__ void k_scatter(const int* __restrict__ src, const int* __restrict__ dst) {
    int i = blockIdx.x * blockDim.x + threadIdx.x;
    if (i < NEDGES) {
        int d = dst[i];
        int p = atomicAdd(&g_wp[d], 1);
        g_col[p] = src[i];
    } else if (i < ETOT) {
        int n = i - NEDGES;
        int p = atomicAdd(&g_wp[n], 1);
        g_col[p] = n;
    }
}
__global__ void k_bptr(const int* __restrict__ batch) {
    int b = threadIdx.x;
    if (b > BATCH) return;
    if (b == BATCH) { g_bptr[BATCH] = NNODES; return; }
    int lo = 0, hi = NNODES;
    while (lo < hi) {
        int mid = (lo + hi) >> 1;
        if (batch[mid] < b) lo = mid + 1; else hi = mid;
    }
    g_bptr[b] = lo;
}

// ---- tf32 MMA GEMM + fused attention dots (pre-converted operands) ----------
#define AST 132
__global__ void __launch_bounds__(256) k_gemm_att(const float* __restrict__ att_src,
                                                  const float* __restrict__ att_dst) {
    __shared__ unsigned As[32][AST];   // [k][m] tf32 bits
    __shared__ unsigned Bs[32][AST];   // [k][n] tf32 bits
    __shared__ float sAs[128], sAd[128];

    const int tid = threadIdx.x;
    const int bm = blockIdx.x * 128;
    const int head = blockIdx.y;         // 0 or 1
    const int bn = head * 128;
    const int wid = tid >> 5, lane = tid & 31;
    const int wm = wid >> 2, wn = wid & 3;   // warp grid 2 x 4
    const int g = lane >> 2, tig = lane & 3;

    if (tid < 128) { sAs[tid] = 0.f; sAd[tid] = 0.f; }

    float c[4][4][4];
#pragma unroll
    for (int mt = 0; mt < 4; mt++)
#pragma unroll
        for (int nt = 0; nt < 4; nt++)
#pragma unroll
            for (int j = 0; j < 4; j++) c[mt][nt][j] = 0.f;

    for (int k0 = 0; k0 < 128; k0 += 32) {
#pragma unroll
        for (int i = 0; i < 4; i++) {
            int slot = tid + i * 256;
            int r = slot >> 3, kq = (slot & 7) * 4;
            uint4 v = *reinterpret_cast<const uint4*>(g_hT + (size_t)(bm + r) * 128 + k0 + kq);
            As[kq + 0][r] = v.x;
            As[kq + 1][r] = v.y;
            As[kq + 2][r] = v.z;
            As[kq + 3][r] = v.w;
        }
#pragma unroll
        for (int i = 0; i < 4; i++) {
            int slot = tid + i * 256;
            int kk = slot >> 5, nq = (slot & 31) * 4;
            uint4 v = *reinterpret_cast<const uint4*>(g_WT + (size_t)(k0 + kk) * 256 + bn + nq);
            *reinterpret_cast<uint4*>(&Bs[kk][nq]) = v;
        }
        __syncthreads();
#pragma unroll
        for (int ks = 0; ks < 4; ks++) {
            int kb = ks * 8;
            unsigned af[4][4], bf[4][2];
#pragma unroll
            for (int mt = 0; mt < 4; mt++) {
                int r0 = wm * 64 + mt * 16 + g;
                af[mt][0] = As[kb + tig][r0];
                af[mt][1] = As[kb + tig][r0 + 8];
                af[mt][2] = As[kb + tig + 4][r0];
                af[mt][3] = As[kb + tig + 4][r0 + 8];
            }
#pragma unroll
            for (int nt = 0; nt < 4; nt++) {
                int c0 = wn * 32 + nt * 8 + g;
                bf[nt][0] = Bs[kb + tig][c0];
                bf[nt][1] = Bs[kb + tig + 4][c0];
            }
#pragma unroll
            for (int mt = 0; mt < 4; mt++)
#pragma unroll
                for (int nt = 0; nt < 4; nt++) {
                    asm volatile(
                        "mma.sync.aligned.m16n8k8.row.col.f32.tf32.tf32.f32 "
                        "{%0,%1,%2,%3}, {%4,%5,%6,%7}, {%8,%9}, {%0,%1,%2,%3};"
                        : "+f"(c[mt][nt][0]), "+f"(c[mt][nt][1]),
                          "+f"(c[mt][nt][2]), "+f"(c[mt][nt][3])
                        : "r"(af[mt][0]), "r"(af[mt][1]), "r"(af[mt][2]), "r"(af[mt][3]),
                          "r"(bf[nt][0]), "r"(bf[nt][1]));
                }
        }
        __syncthreads();
    }

    float asr[8], adr[8];
#pragma unroll
    for (int nt = 0; nt < 4; nt++) {
#pragma unroll
        for (int j = 0; j < 2; j++) {
            int col = wn * 32 + nt * 8 + tig * 2 + j;
            asr[nt * 2 + j] = att_src[head * 128 + col];
            adr[nt * 2 + j] = att_dst[head * 128 + col];
        }
    }

#pragma unroll
    for (int mt = 0; mt < 4; mt++) {
#pragma unroll
        for (int half = 0; half < 2; half++) {
            int lr = wm * 64 + mt * 16 + g + half * 8;
            int row = bm + lr;
            float ds = 0.f, dd = 0.f;
#pragma unroll
            for (int nt = 0; nt < 4; nt++) {
                float v0 = c[mt][nt][half * 2];
                float v1 = c[mt][nt][half * 2 + 1];
                int col = bn + wn * 32 + nt * 8 + tig * 2;
                *reinterpret_cast<float2*>(g_xl + (size_t)row * 256 + col) = make_float2(v0, v1);
                ds += v0 * asr[nt * 2] + v1 * asr[nt * 2 + 1];
                dd += v0 * adr[nt * 2] + v1 * adr[nt * 2 + 1];
            }
            ds += __shfl_xor_sync(0xffffffffu, ds, 1);
            ds += __shfl_xor_sync(0xffffffffu, ds, 2);
            dd += __shfl_xor_sync(0xffffffffu, dd, 1);
            dd += __shfl_xor_sync(0xffffffffu, dd, 2);
            if (tig == 0) {
                atomicAdd(&sAs[lr], ds);
                atomicAdd(&sAd[lr], dd);
            }
        }
    }
    __syncthreads();
    if (tid < 128) {
        g_asrc[(size_t)(bm + tid) * 2 + head] = sAs[tid];
        g_adst[(size_t)(bm + tid) * 2 + head] = sAd[tid];
    }
}

// ------- softmax-aggregate: warp per (node, head); warp pairs combine --------
__global__ void __launch_bounds__(256) k_aggregate(const float* __restrict__ bias,
                                                   float* __restrict__ out) {
    __shared__ float wbuf[8][CAP];
    __shared__ float stage[4][DIM];

    const int tid = threadIdx.x;
    const int wid = tid >> 5, lane = tid & 31;
    const int pairId = wid >> 1;
    const int head = wid & 1;
    const int node = blockIdx.x * 4 + pairId;
    const bool active = node < NNODES;

    int p0 = 0, L = 0;
    float ad = 0.f;
    if (active) {
        p0 = g_rowptr[node];
        L = g_rowptr[node + 1] - p0;
        ad = g_adst[node * 2 + head];
    }

    // pass A: weights + sum
    float s = 0.f;
    if (active) {
        if (L <= CAP) {
            for (int q = lane; q < L; q += 32) {
                int si = g_col[p0 + q];
                float e = __expf(lrelu(g_asrc[si * 2 + head] + ad));
                wbuf[wid][q] = e;
                s += e;
            }
        } else {
            for (int q = lane; q < L; q += 32) {
                int si = g_col[p0 + q];
                float e = __expf(lrelu(g_asrc[si * 2 + head] + ad));
                g_ew[(size_t)head * ETOT + p0 + q] = e;
                s += e;
            }
        }
        s = wred_sum(s);
    }
    __syncwarp();
    float inv = 1.f / (s + 1e-16f);

    // pass B: weighted gather of this head's 512B rows
    float4 a = make_float4(0.f, 0.f, 0.f, 0.f);
    if (active) {
        if (L <= CAP) {
            for (int q = 0; q < L; q++) {
                int si = g_col[p0 + q];
                float w = wbuf[wid][q];
                float4 v = reinterpret_cast<const float4*>(g_xl + (size_t)si * 256 + head * 128)[lane];
                a.x += w * v.x; a.y += w * v.y; a.z += w * v.z; a.w += w * v.w;
            }
        } else {
            for (int q = 0; q < L; q++) {
                int si = g_col[p0 + q];
                float w = g_ew[(size_t)head * ETOT + p0 + q];
                float4 v = reinterpret_cast<const float4*>(g_xl + (size_t)si * 256 + head * 128)[lane];
                a.x += w * v.x; a.y += w * v.y; a.z += w * v.z; a.w += w * v.w;
            }
        }
    }

    // combine heads
    if (active && head == 1) {
        *reinterpret_cast<float4*>(&stage[pairId][lane * 4]) =
            make_float4(a.x * inv, a.y * inv, a.z * inv, a.w * inv);
    }
    __syncthreads();
    if (active && head == 0) {
        float4 v1 = *reinterpret_cast<const float4*>(&stage[pairId][lane * 4]);
        float4 bv = reinterpret_cast<const float4*>(bias)[lane];
        float4 o;
        o.x = 0.5f * (a.x * inv + v1.x) + bv.x;
        o.y = 0.5f * (a.y * inv + v1.y) + bv.y;
        o.z = 0.5f * (a.z * inv + v1.z) + bv.z;
        o.w = 0.5f * (a.w * inv + v1.w) + bv.w;
        *reinterpret_cast<float4*>(out + (size_t)node * DIM + lane * 4) = o;
        uint4 u;
        u.x = f2tf32(o.x); u.y = f2tf32(o.y); u.z = f2tf32(o.z); u.w = f2tf32(o.w);
        *reinterpret_cast<uint4*>(g_hT + (size_t)node * DIM + lane * 4) = u;
    }
}

// ---------------- Set2Set ----------------------------------------------------
__global__ void k_zero_s2s() {
    int i = blockIdx.x * blockDim.x + threadIdx.x;
    if (i < BATCH * 256) g_qstar[i] = 0.f;
    else if (i < BATCH * 256 + BATCH * 128) g_lq[i - BATCH * 256] = 0.f;
    else if (i < BATCH * 256 + 2 * BATCH * 128) g_lc[i - BATCH * 256 - BATCH * 128] = 0.f;
}

__global__ void __launch_bounds__(512) k_lstm(const float* __restrict__ Wih,
                                              const float* __restrict__ Whh,
                                              const float* __restrict__ bih,
                                              const float* __restrict__ bhh) {
    int b = blockIdx.x;
    int tid = threadIdx.x;
    __shared__ float qs[256];
    __shared__ float hs[128];
    __shared__ float gates[512];
    if (tid < 256) qs[tid] = g_qstar[b * 256 + tid];
    else if (tid < 384) hs[tid - 256] = g_lq[b * 128 + (tid - 256)];
    __syncthreads();
    float acc = bih[tid] + bhh[tid];
    const float4* wi = reinterpret_cast<const float4*>(Wih + (size_t)tid * 256);
#pragma unroll 8
    for (int k = 0; k < 64; k++) {
        float4 w = wi[k];
        acc += w.x * qs[k * 4] + w.y * qs[k * 4 + 1] + w.z * qs[k * 4 + 2] + w.w * qs[k * 4 + 3];
    }
    const float4* wh = reinterpret_cast<const float4*>(Whh + (size_t)tid * 128);
#pragma unroll 8
    for (int k = 0; k < 32; k++) {
        float4 w = wh[k];
        acc += w.x * hs[k * 4] + w.y * hs[k * 4 + 1] + w.z * hs[k * 4 + 2] + w.w * hs[k * 4 + 3];
    }
    gates[tid] = acc;
    __syncthreads();
    if (tid < 128) {
        float gi = 1.f / (1.f + __expf(-gates[tid]));
        float gf = 1.f / (1.f + __expf(-gates[128 + tid]));
        float gg = tanhf(gates[256 + tid]);
        float go = 1.f / (1.f + __expf(-gates[384 + tid]));
        float c2 = gf * g_lc[b * 128 + tid] + gi * gg;
        float q = go * tanhf(c2);
        g_lc[b * 128 + tid] = c2;
        g_lq[b * 128 + tid] = q;
        g_qstar[b * 256 + tid] = q;
    }
}

__global__ void k_e(const float* __restrict__ h, const int* __restrict__ batch) {
    int gw = (blockIdx.x * blockDim.x + threadIdx.x) >> 5;
    int lane = threadIdx.x & 31;
    if (gw >= NNODES) return;
    int b = batch[gw];
    float4 hv = reinterpret_cast<const float4*>(h + (size_t)gw * DIM)[lane];
    float4 qv = reinterpret_cast<const float4*>(g_lq + (size_t)b * DIM)[lane];
    float r = hv.x * qv.x + hv.y * qv.y + hv.z * qv.z + hv.w * qv.w;
    r = wred_sum(r);
    if (lane == 0) g_e[gw] = r;
}

__global__ void __launch_bounds__(256) k_segstat() {
    int b = blockIdx.x;
    int tid = threadIdx.x;
    int p0 = g_bptr[b], p1 = g_bptr[b + 1];
    __shared__ float red[256];
    float m = -1e30f;
    for (int n = p0 + tid; n < p1; n += 256) m = fmaxf(m, g_e[n]);
    red[tid] = m;
    __syncthreads();
    for (int off = 128; off > 0; off >>= 1) {
        if (tid < off) red[tid] = fmaxf(red[tid], red[tid + off]);
        __syncthreads();
    }
    m = red[0];
    __syncthreads();
    float s = 0.f;
    for (int n = p0 + tid; n < p1; n += 256) s += __expf(g_e[n] - m);
    red[tid] = s;
    __syncthreads();
    for (int off = 128; off > 0; off >>= 1) {
        if (tid < off) red[tid] += red[tid + off];
        __syncthreads();
    }
    if (tid == 0) {
        g_sm[b] = m;
        g_sinv[b] = 1.f / (red[0] + 1e-16f);
    }
}

// chunked weighted segment reduce with inline softmax weight
__global__ void __launch_bounds__(128) k_rpart(const float* __restrict__ h) {
    int b = blockIdx.x;
    int ch = blockIdx.y;
    int d = threadIdx.x;
    int p0 = g_bptr[b], p1 = g_bptr[b + 1];
    int L = p1 - p0;
    int per = (L + RCH - 1) / RCH;
    int st = p0 + ch * per;
    int en = min(st + per, p1);
    float m = g_sm[b], si = g_sinv[b];
    float acc = 0.f;
    for (int n = st; n < en; n++)
        acc += __expf(g_e[n] - m) * si * h[(size_t)n * DIM + d];
    g_rpart[((size_t)b * RCH + ch) * DIM + d] = acc;
}
__global__ void __launch_bounds__(128) k_rred() {
    int b = blockIdx.x;
    int d = threadIdx.x;
    float acc = 0.f;
#pragma unroll
    for (int ch = 0; ch < RCH; ch++) acc += g_rpart[((size_t)b * RCH + ch) * DIM + d];
    g_qstar[b * 256 + 128 + d] = acc;
}

// ---------------- final MLP --------------------------------------------------
__global__ void __launch_bounds__(128) k_mlp(const float* __restrict__ W1, const float* __restrict__ b1,
                                             const float* __restrict__ W2, const float* __restrict__ b2,
                                             float* __restrict__ out) {
    int b = blockIdx.x;
    int j = threadIdx.x;
    __shared__ float qs[256];
    __shared__ float hid[128];
    qs[j] = g_qstar[b * 256 + j];
    qs[128 + j] = g_qstar[b * 256 + 128 + j];
    __syncthreads();
    float acc = b1[j];
#pragma unroll 8
    for (int k = 0; k < 256; k++) acc += qs[k] * W1[k * 128 + j];
    hid[j] = fmaxf(acc, 0.f);
    __syncthreads();
    float acc2 = b2[j];
#pragma unroll 8
    for (int k = 0; k < 128; k++) acc2 += hid[k] * W2[k * 128 + j];
    out[b * 128 + j] = acc2;
}

// ---------------- launch -----------------------------------------------------
extern "C" void kernel_launch(void* const* d_in, const int* in_sizes, int n_in,
                              void* d_out, int out_size) {
    const float* x        = (const float*)d_in[0];
    const int*   ei       = (const int*)d_in[1];     // int64 inputs delivered as int32
    const int*   batch    = (const int*)d_in[3];
    const float* gat_W    = (const float*)d_in[4];
    const float* att_src  = (const float*)d_in[5];
    const float* att_dst  = (const float*)d_in[6];
    const float* gat_bias = (const float*)d_in[7];
    const float* Wih      = (const float*)d_in[8];
    const float* Whh      = (const float*)d_in[9];
    const float* bih      = (const float*)d_in[10];
    const float* bhh      = (const float*)d_in[11];
    const float* W1       = (const float*)d_in[12];
    const float* b1       = (const float*)d_in[13];
    const float* W2       = (const float*)d_in[14];
    const float* b2       = (const float*)d_in[15];
    float*       out      = (float*)d_out;

    const int* src = ei;
    const int* dst = ei + NEDGES;

    float* hA = nullptr;
    float* hB = nullptr;
    cudaGetSymbolAddress((void**)&hA, g_hA);
    cudaGetSymbolAddress((void**)&hB, g_hB);

    const int warpBlocks = (NNODES * 32 + 255) / 256;
    const int aggBlocks = (NNODES + 3) / 4;
    dim3 gg(NPAD / 128, 2);

    // order chosen so launch #4 is k_gemm_att (ncu fixed-window profiling)
    k_init_h<<<(NPAD * (DIM / 4) + 255) / 256, 256>>>(x);
    k_cvtW<<<(DIM * 2 * DIM + 255) / 256, 256>>>(gat_W);
    k_hist<<<(NEDGES + 255) / 256, 256>>>(dst);
    k_gemm_att<<<gg, 256>>>(att_src, att_dst);            // conv0 GEMM
    k_scan1<<<NCHUNK, 256>>>();
    k_scan2<<<1, 256>>>();
    k_scan3<<<NCHUNK, 256>>>();
    k_scatter<<<(ETOT + 255) / 256, 256>>>(src, dst);
    k_bptr<<<1, 256>>>(batch);
    k_zero_s2s<<<(BATCH * 512 + 255) / 256, 256>>>();

    float* cur = hA;
    float* nxt = hB;
    for (int c = 0; c < 3; c++) {
        if (c > 0) k_gemm_att<<<gg, 256>>>(att_src, att_dst);
        k_aggregate<<<aggBlocks, 256>>>(gat_bias, nxt);
        float* t = cur; cur = nxt; nxt = t;
    }

    for (int s = 0; s < 3; s++) {
        k_lstm<<<BATCH, 512>>>(Wih, Whh, bih, bhh);
        k_e<<<warpBlocks, 256>>>(cur, batch);
        k_segstat<<<BATCH, 256>>>();
        dim3 rg(BATCH, RCH);
        k_rpart<<<rg, 128>>>(cur);
        k_rred<<<BATCH, 128>>>();
    }

    k_mlp<<<BATCH, 128>>>(W1, b1, W2, b2, out);
}

// round 7
// speedup vs baseline: 1.5909x; 1.0277x over previous
#include <cuda_runtime.h>
#include <math.h>

#define NNODES 50000
#define NPAD   50048              // 391 * 128
#define NEDGES 800000
#define ETOT   (NEDGES + NNODES)  // edges + self loops
#define BATCH  128
#define DIM    128
#define NEG_SLOPE 0.2f
#define NCHUNK 196                // ceil(50000/256)
#define RCH    8                  // k_r chunks per segment
#define CAP    128                // smem weight stash per warp

// ---------------- scratch (device globals) ----------------------------------
__device__ float    g_hA[NPAD * DIM];
__device__ float    g_hB[NPAD * DIM];
__device__ unsigned g_hT[NPAD * DIM];          // tf32 copy of current h
__device__ unsigned g_WT[DIM * 2 * DIM];       // tf32 copy of gat_W
__device__ float    g_xl[(size_t)NPAD * 2 * DIM];
__device__ float    g_asrc[NPAD * 2];
__device__ float    g_adst[NPAD * 2];
__device__ int      g_deg[NNODES];
__device__ int      g_rowptr[NNODES + 1];
__device__ int      g_wp[NNODES];
__device__ int      g_col[ETOT];
__device__ float    g_ew[(size_t)2 * ETOT];    // [head][edge] fallback
__device__ int      g_bsum[256];
__device__ int      g_bbase[256];
__device__ int      g_bptr[BATCH + 1];
__device__ float    g_qstar[BATCH * 2 * DIM];
__device__ float    g_lq[BATCH * DIM];
__device__ float    g_lc[BATCH * DIM];
__device__ float    g_e[NNODES];
__device__ float    g_sm[BATCH];
__device__ float    g_sinv[BATCH];
__device__ float    g_rpart[BATCH * RCH * DIM];

// ---------------- helpers ---------------------------------------------------
__device__ __forceinline__ float wred_sum(float v) {
#pragma unroll
    for (int o = 16; o > 0; o >>= 1) v += __shfl_xor_sync(0xffffffffu, v, o);
    return v;
}
__device__ __forceinline__ float lrelu(float v) { return v > 0.f ? v : NEG_SLOPE * v; }
__device__ __forceinline__ unsigned f2tf32(float f) {
    unsigned u;
    asm("cvt.rna.tf32.f32 %0, %1;" : "=r"(u) : "f"(f));
    return u;
}

// ---------------- input padding + deg init + tf32 copy ----------------------
__global__ void k_init_h(const float* __restrict__ x) {
    int i = blockIdx.x * blockDim.x + threadIdx.x;  // float4 index
    if (i >= NPAD * (DIM / 4)) return;
    int n = i >> 5;
    int c = (i & 31) * 4;
    float4 v = make_float4(0.f, 0.f, 0.f, 0.f);
    if (n < NNODES) {
        if (c + 0 < 9) v.x = x[n * 9 + c + 0];
        if (c + 1 < 9) v.y = x[n * 9 + c + 1];
        if (c + 2 < 9) v.z = x[n * 9 + c + 2];
        if (c + 3 < 9) v.w = x[n * 9 + c + 3];
        if ((i & 31) == 0) g_deg[n] = 1;  // self loop
    }
    reinterpret_cast<float4*>(g_hA)[i] = v;
    uint4 u;
    u.x = f2tf32(v.x); u.y = f2tf32(v.y); u.z = f2tf32(v.z); u.w = f2tf32(v.w);
    reinterpret_cast<uint4*>(g_hT)[i] = u;
}

__global__ void k_cvtW(const float* __restrict__ W) {
    int i = blockIdx.x * blockDim.x + threadIdx.x;
    if (i < DIM * 2 * DIM) g_WT[i] = f2tf32(W[i]);
}

// ---------------- CSR build --------------------------------------------------
__global__ void k_hist(const int* __restrict__ dst) {
    int e = blockIdx.x * blockDim.x + threadIdx.x;
    if (e < NEDGES) atomicAdd(&g_deg[dst[e]], 1);
}
__global__ void __launch_bounds__(256) k_scan1() {
    __shared__ int ss[256];
    int t = threadIdx.x;
    int idx = blockIdx.x * 256 + t;
    ss[t] = (idx < NNODES) ? g_deg[idx] : 0;
    __syncthreads();
    for (int off = 128; off > 0; off >>= 1) {
        if (t < off) ss[t] += ss[t + off];
        __syncthreads();
    }
    if (t == 0) g_bsum[blockIdx.x] = ss[0];
}
__global__ void __launch_bounds__(256) k_scan2() {
    __shared__ int ss[256];
    int t = threadIdx.x;
    int v = (t < NCHUNK) ? g_bsum[t] : 0;
    ss[t] = v;
    __syncthreads();
    for (int off = 1; off < 256; off <<= 1) {
        int x = (t >= off) ? ss[t - off] : 0;
        __syncthreads();
        ss[t] += x;
        __syncthreads();
    }
    if (t < NCHUNK) g_bbase[t] = ss[t] - v;  // exclusive
}
__global__ void __launch_bounds__(256) k_scan3() {
    __shared__ int ss[256];
    int t = threadIdx.x;
    int idx = blockIdx.x * 256 + t;
    int v = (idx < NNODES) ? g_deg[idx] : 0;
    ss[t] = v;
    __syncthreads();
    for (int off = 1; off < 256; off <<= 1) {
        int x = (t >= off) ? ss[t - off] : 0;
        __syncthreads();
        ss[t] += x;
        __syncthreads();
    }
    if (idx < NNODES) {
        int r = g_bbase[blockIdx.x] + ss[t] - v;
        g_rowptr[idx] = r;
        g_wp[idx] = r;
    }
    if (idx == 0) g_rowptr[NNODES] = ETOT;
}
__global__ void k_scatter(const int* __restrict__ src, const int* __restrict__ dst) {
    int i = blockIdx.x * blockDim.x + threadIdx.x;
    if (i < NEDGES) {
        int d = dst[i];
        int p = atomicAdd(&g_wp[d], 1);
        g_col[p] = src[i];
    } else if (i < ETOT) {
        int n = i - NEDGES;
        int p = atomicAdd(&g_wp[n], 1);
        g_col[p] = n;
    }
}
__global__ void k_bptr(const int* __restrict__ batch) {
    int b = threadIdx.x;
    if (b > BATCH) return;
    if (b == BATCH) { g_bptr[BATCH] = NNODES; return; }
    int lo = 0, hi = NNODES;
    while (lo < hi) {
        int mid = (lo + hi) >> 1;
        if (batch[mid] < b) lo = mid + 1; else hi = mid;
    }
    g_bptr[b] = lo;
}

// ---- tf32 MMA GEMM + fused attention dots -----------------------------------
// A smem: pair-packed layout. AsPw word offset = r*34 + tig*8 + ks*2 (+half)
// holds (A[r][8ks+tig], A[r][8ks+tig+4]) as adjacent 4B words (one uint2).
// Fragment fetch: 2x LDS.64 per mt per ks, conflict-free (g + 4*tig mod 16).
#define AST 132
__global__ void __launch_bounds__(256) k_gemm_att(const float* __restrict__ att_src,
                                                  const float* __restrict__ att_dst) {
    __shared__ unsigned AsPw[128 * 34];   // 17 uint2 per row (16 pairs + 1 pad)
    __shared__ unsigned Bs[32][AST];      // [k][n] tf32 bits
    __shared__ float sAs[128], sAd[128];

    const int tid = threadIdx.x;
    const int bm = blockIdx.x * 128;
    const int head = blockIdx.y;         // 0 or 1
    const int bn = head * 128;
    const int wid = tid >> 5, lane = tid & 31;
    const int wm = wid >> 2, wn = wid & 3;   // warp grid 2 x 4
    const int g = lane >> 2, tig = lane & 3;

    if (tid < 128) { sAs[tid] = 0.f; sAd[tid] = 0.f; }

    float c[4][4][4];
#pragma unroll
    for (int mt = 0; mt < 4; mt++)
#pragma unroll
        for (int nt = 0; nt < 4; nt++)
#pragma unroll
            for (int j = 0; j < 4; j++) c[mt][nt][j] = 0.f;

    for (int k0 = 0; k0 < 128; k0 += 32) {
        // stage A (pair-packed)
#pragma unroll
        for (int i = 0; i < 4; i++) {
            int slot = tid + i * 256;
            int r = slot >> 3, kq = (slot & 7) * 4;     // kq in {0,4,...,28}
            uint4 v = *reinterpret_cast<const uint4*>(g_hT + (size_t)(bm + r) * 128 + k0 + kq);
            int ks = kq >> 3;
            int half = (kq >> 2) & 1;                    // 0 -> .x slot, 1 -> .y slot
            unsigned* base = &AsPw[r * 34 + ks * 2 + half];
            base[0 * 8] = v.x;
            base[1 * 8] = v.y;
            base[2 * 8] = v.z;
            base[3 * 8] = v.w;
        }
        // stage B ([k][n])
#pragma unroll
        for (int i = 0; i < 4; i++) {
            int slot = tid + i * 256;
            int kk = slot >> 5, nq = (slot & 31) * 4;
            uint4 v = *reinterpret_cast<const uint4*>(g_WT + (size_t)(k0 + kk) * 256 + bn + nq);
            *reinterpret_cast<uint4*>(&Bs[kk][nq]) = v;
        }
        __syncthreads();
#pragma unroll
        for (int ks = 0; ks < 4; ks++) {
            int kb = ks * 8;
            unsigned af[4][4], bf[4][2];
            const uint2* AsP = reinterpret_cast<const uint2*>(AsPw);
#pragma unroll
            for (int mt = 0; mt < 4; mt++) {
                int r0 = wm * 64 + mt * 16 + g;
                uint2 lo = AsP[r0 * 17 + tig * 4 + ks];
                uint2 hi = AsP[(r0 + 8) * 17 + tig * 4 + ks];
                af[mt][0] = lo.x; af[mt][1] = hi.x;
                af[mt][2] = lo.y; af[mt][3] = hi.y;
            }
#pragma unroll
            for (int nt = 0; nt < 4; nt++) {
                int c0 = wn * 32 + nt * 8 + g;
                bf[nt][0] = Bs[kb + tig][c0];
                bf[nt][1] = Bs[kb + tig + 4][c0];
            }
#pragma unroll
            for (int mt = 0; mt < 4; mt++)
#pragma unroll
                for (int nt = 0; nt < 4; nt++) {
                    asm volatile(
                        "mma.sync.aligned.m16n8k8.row.col.f32.tf32.tf32.f32 "
                        "{%0,%1,%2,%3}, {%4,%5,%6,%7}, {%8,%9}, {%0,%1,%2,%3};"
                        : "+f"(c[mt][nt][0]), "+f"(c[mt][nt][1]),
                          "+f"(c[mt][nt][2]), "+f"(c[mt][nt][3])
                        : "r"(af[mt][0]), "r"(af[mt][1]), "r"(af[mt][2]), "r"(af[mt][3]),
                          "r"(bf[nt][0]), "r"(bf[nt][1]));
                }
        }
        __syncthreads();
    }

    float asr[8], adr[8];
#pragma unroll
    for (int nt = 0; nt < 4; nt++) {
#pragma unroll
        for (int j = 0; j < 2; j++) {
            int col = wn * 32 + nt * 8 + tig * 2 + j;
            asr[nt * 2 + j] = att_src[head * 128 + col];
            adr[nt * 2 + j] = att_dst[head * 128 + col];
        }
    }

#pragma unroll
    for (int mt = 0; mt < 4; mt++) {
#pragma unroll
        for (int half = 0; half < 2; half++) {
            int lr = wm * 64 + mt * 16 + g + half * 8;
            int row = bm + lr;
            float ds = 0.f, dd = 0.f;
#pragma unroll
            for (int nt = 0; nt < 4; nt++) {
                float v0 = c[mt][nt][half * 2];
                float v1 = c[mt][nt][half * 2 + 1];
                int col = bn + wn * 32 + nt * 8 + tig * 2;
                *reinterpret_cast<float2*>(g_xl + (size_t)row * 256 + col) = make_float2(v0, v1);
                ds += v0 * asr[nt * 2] + v1 * asr[nt * 2 + 1];
                dd += v0 * adr[nt * 2] + v1 * adr[nt * 2 + 1];
            }
            ds += __shfl_xor_sync(0xffffffffu, ds, 1);
            ds += __shfl_xor_sync(0xffffffffu, ds, 2);
            dd += __shfl_xor_sync(0xffffffffu, dd, 1);
            dd += __shfl_xor_sync(0xffffffffu, dd, 2);
            if (tig == 0) {
                atomicAdd(&sAs[lr], ds);
                atomicAdd(&sAd[lr], dd);
            }
        }
    }
    __syncthreads();
    if (tid < 128) {
        g_asrc[(size_t)(bm + tid) * 2 + head] = sAs[tid];
        g_adst[(size_t)(bm + tid) * 2 + head] = sAd[tid];
    }
}

// ------- softmax-aggregate: warp per (node, head); 4-deep gather pipeline ----
__global__ void __launch_bounds__(256) k_aggregate(const float* __restrict__ bias,
                                                   float* __restrict__ out) {
    __shared__ float wbuf[8][CAP];
    __shared__ float stage[4][DIM];

    const int tid = threadIdx.x;
    const int wid = tid >> 5, lane = tid & 31;
    const int pairId = wid >> 1;
    const int head = wid & 1;
    const int node = blockIdx.x * 4 + pairId;
    const bool active = node < NNODES;

    int p0 = 0, L = 0;
    float ad = 0.f;
    if (active) {
        p0 = g_rowptr[node];
        L = g_rowptr[node + 1] - p0;
        ad = g_adst[node * 2 + head];
    }
    const bool inCap = (L <= CAP);

    // pass A: weights + sum
    float s = 0.f;
    if (active) {
        if (inCap) {
            for (int q = lane; q < L; q += 32) {
                int si = g_col[p0 + q];
                float e = __expf(lrelu(g_asrc[si * 2 + head] + ad));
                wbuf[wid][q] = e;
                s += e;
            }
        } else {
            for (int q = lane; q < L; q += 32) {
                int si = g_col[p0 + q];
                float e = __expf(lrelu(g_asrc[si * 2 + head] + ad));
                g_ew[(size_t)head * ETOT + p0 + q] = e;
                s += e;
            }
        }
        s = wred_sum(s);
    }
    __syncwarp();
    float inv = 1.f / (s + 1e-16f);

    // pass B: weighted gather, 4 independent row loads in flight
    float4 a = make_float4(0.f, 0.f, 0.f, 0.f);
    if (active) {
        const float* xb = g_xl + head * 128;
        int q = 0;
        for (; q + 4 <= L; q += 4) {
            int si0 = g_col[p0 + q + 0];
            int si1 = g_col[p0 + q + 1];
            int si2 = g_col[p0 + q + 2];
            int si3 = g_col[p0 + q + 3];
            float4 v0 = reinterpret_cast<const float4*>(xb + (size_t)si0 * 256)[lane];
            float4 v1 = reinterpret_cast<const float4*>(xb + (size_t)si1 * 256)[lane];
            float4 v2 = reinterpret_cast<const float4*>(xb + (size_t)si2 * 256)[lane];
            float4 v3 = reinterpret_cast<const float4*>(xb + (size_t)si3 * 256)[lane];
            float w0, w1, w2, w3;
            if (inCap) {
                w0 = wbuf[wid][q + 0]; w1 = wbuf[wid][q + 1];
                w2 = wbuf[wid][q + 2]; w3 = wbuf[wid][q + 3];
            } else {
                w0 = g_ew[(size_t)head * ETOT + p0 + q + 0];
                w1 = g_ew[(size_t)head * ETOT + p0 + q + 1];
                w2 = g_ew[(size_t)head * ETOT + p0 + q + 2];
                w3 = g_ew[(size_t)head * ETOT + p0 + q + 3];
            }
            a.x += w0 * v0.x; a.y += w0 * v0.y; a.z += w0 * v0.z; a.w += w0 * v0.w;
            a.x += w1 * v1.x; a.y += w1 * v1.y; a.z += w1 * v1.z; a.w += w1 * v1.w;
            a.x += w2 * v2.x; a.y += w2 * v2.y; a.z += w2 * v2.z; a.w += w2 * v2.w;
            a.x += w3 * v3.x; a.y += w3 * v3.y; a.z += w3 * v3.z; a.w += w3 * v3.w;
        }
        for (; q < L; q++) {
            int si = g_col[p0 + q];
            float w = inCap ? wbuf[wid][q] : g_ew[(size_t)head * ETOT + p0 + q];
            float4 v = reinterpret_cast<const float4*>(xb + (size_t)si * 256)[lane];
            a.x += w * v.x; a.y += w * v.y; a.z += w * v.z; a.w += w * v.w;
        }
    }

    // combine heads
    if (active && head == 1) {
        *reinterpret_cast<float4*>(&stage[pairId][lane * 4]) =
            make_float4(a.x * inv, a.y * inv, a.z * inv, a.w * inv);
    }
    __syncthreads();
    if (active && head == 0) {
        float4 v1 = *reinterpret_cast<const float4*>(&stage[pairId][lane * 4]);
        float4 bv = reinterpret_cast<const float4*>(bias)[lane];
        float4 o;
        o.x = 0.5f * (a.x * inv + v1.x) + bv.x;
        o.y = 0.5f * (a.y * inv + v1.y) + bv.y;
        o.z = 0.5f * (a.z * inv + v1.z) + bv.z;
        o.w = 0.5f * (a.w * inv + v1.w) + bv.w;
        *reinterpret_cast<float4*>(out + (size_t)node * DIM + lane * 4) = o;
        uint4 u;
        u.x = f2tf32(o.x); u.y = f2tf32(o.y); u.z = f2tf32(o.z); u.w = f2tf32(o.w);
        *reinterpret_cast<uint4*>(g_hT + (size_t)node * DIM + lane * 4) = u;
    }
}

// ---------------- Set2Set ----------------------------------------------------
__global__ void k_zero_s2s() {
    int i = blockIdx.x * blockDim.x + threadIdx.x;
    if (i < BATCH * 256) g_qstar[i] = 0.f;
    else if (i < BATCH * 256 + BATCH * 128) g_lq[i - BATCH * 256] = 0.f;
    else if (i < BATCH * 256 + 2 * BATCH * 128) g_lc[i - BATCH * 256 - BATCH * 128] = 0.f;
}

__global__ void __launch_bounds__(512) k_lstm(const float* __restrict__ Wih,
                                              const float* __restrict__ Whh,
                                              const float* __restrict__ bih,
                                              const float* __restrict__ bhh) {
    int b = blockIdx.x;
    int tid = threadIdx.x;
    __shared__ float qs[256];
    __shared__ float hs[128];
    __shared__ float gates[512];
    if (tid < 256) qs[tid] = g_qstar[b * 256 + tid];
    else if (tid < 384) hs[tid - 256] = g_lq[b * 128 + (tid - 256)];
    __syncthreads();
    float acc = bih[tid] + bhh[tid];
    const float4* wi = reinterpret_cast<const float4*>(Wih + (size_t)tid * 256);
#pragma unroll 8
    for (int k = 0; k < 64; k++) {
        float4 w = wi[k];
        acc += w.x * qs[k * 4] + w.y * qs[k * 4 + 1] + w.z * qs[k * 4 + 2] + w.w * qs[k * 4 + 3];
    }
    const float4* wh = reinterpret_cast<const float4*>(Whh + (size_t)tid * 128);
#pragma unroll 8
    for (int k = 0; k < 32; k++) {
        float4 w = wh[k];
        acc += w.x * hs[k * 4] + w.y * hs[k * 4 + 1] + w.z * hs[k * 4 + 2] + w.w * hs[k * 4 + 3];
    }
    gates[tid] = acc;
    __syncthreads();
    if (tid < 128) {
        float gi = 1.f / (1.f + __expf(-gates[tid]));
        float gf = 1.f / (1.f + __expf(-gates[128 + tid]));
        float gg = tanhf(gates[256 + tid]);
        float go = 1.f / (1.f + __expf(-gates[384 + tid]));
        float c2 = gf * g_lc[b * 128 + tid] + gi * gg;
        float q = go * tanhf(c2);
        g_lc[b * 128 + tid] = c2;
        g_lq[b * 128 + tid] = q;
        g_qstar[b * 256 + tid] = q;
    }
}

__global__ void k_e(const float* __restrict__ h, const int* __restrict__ batch) {
    int gw = (blockIdx.x * blockDim.x + threadIdx.x) >> 5;
    int lane = threadIdx.x & 31;
    if (gw >= NNODES) return;
    int b = batch[gw];
    float4 hv = reinterpret_cast<const float4*>(h + (size_t)gw * DIM)[lane];
    float4 qv = reinterpret_cast<const float4*>(g_lq + (size_t)b * DIM)[lane];
    float r = hv.x * qv.x + hv.y * qv.y + hv.z * qv.z + hv.w * qv.w;
    r = wred_sum(r);
    if (lane == 0) g_e[gw] = r;
}

__global__ void __launch_bounds__(256) k_segstat() {
    int b = blockIdx.x;
    int tid = threadIdx.x;
    int p0 = g_bptr[b], p1 = g_bptr[b + 1];
    __shared__ float red[256];
    float m = -1e30f;
    for (int n = p0 + tid; n < p1; n += 256) m = fmaxf(m, g_e[n]);
    red[tid] = m;
    __syncthreads();
    for (int off = 128; off > 0; off >>= 1) {
        if (tid < off) red[tid] = fmaxf(red[tid], red[tid + off]);
        __syncthreads();
    }
    m = red[0];
    __syncthreads();
    float s = 0.f;
    for (int n = p0 + tid; n < p1; n += 256) s += __expf(g_e[n] - m);
    red[tid] = s;
    __syncthreads();
    for (int off = 128; off > 0; off >>= 1) {
        if (tid < off) red[tid] += red[tid + off];
        __syncthreads();
    }
    if (tid == 0) {
        g_sm[b] = m;
        g_sinv[b] = 1.f / (red[0] + 1e-16f);
    }
}

__global__ void __launch_bounds__(128) k_rpart(const float* __restrict__ h) {
    int b = blockIdx.x;
    int ch = blockIdx.y;
    int d = threadIdx.x;
    int p0 = g_bptr[b], p1 = g_bptr[b + 1];
    int L = p1 - p0;
    int per = (L + RCH - 1) / RCH;
    int st = p0 + ch * per;
    int en = min(st + per, p1);
    float m = g_sm[b], si = g_sinv[b];
    float acc = 0.f;
    for (int n = st; n < en; n++)
        acc += __expf(g_e[n] - m) * si * h[(size_t)n * DIM + d];
    g_rpart[((size_t)b * RCH + ch) * DIM + d] = acc;
}
__global__ void __launch_bounds__(128) k_rred() {
    int b = blockIdx.x;
    int d = threadIdx.x;
    float acc = 0.f;
#pragma unroll
    for (int ch = 0; ch < RCH; ch++) acc += g_rpart[((size_t)b * RCH + ch) * DIM + d];
    g_qstar[b * 256 + 128 + d] = acc;
}

// ---------------- final MLP --------------------------------------------------
__global__ void __launch_bounds__(128) k_mlp(const float* __restrict__ W1, const float* __restrict__ b1,
                                             const float* __restrict__ W2, const float* __restrict__ b2,
                                             float* __restrict__ out) {
    int b = blockIdx.x;
    int j = threadIdx.x;
    __shared__ float qs[256];
    __shared__ float hid[128];
    qs[j] = g_qstar[b * 256 + j];
    qs[128 + j] = g_qstar[b * 256 + 128 + j];
    __syncthreads();
    float acc = b1[j];
#pragma unroll 8
    for (int k = 0; k < 256; k++) acc += qs[k] * W1[k * 128 + j];
    hid[j] = fmaxf(acc, 0.f);
    __syncthreads();
    float acc2 = b2[j];
#pragma unroll 8
    for (int k = 0; k < 128; k++) acc2 += hid[k] * W2[k * 128 + j];
    out[b * 128 + j] = acc2;
}

// ---------------- launch -----------------------------------------------------
extern "C" void kernel_launch(void* const* d_in, const int* in_sizes, int n_in,
                              void* d_out, int out_size) {
    const float* x        = (const float*)d_in[0];
    const int*   ei       = (const int*)d_in[1];     // int64 inputs delivered as int32
    const int*   batch    = (const int*)d_in[3];
    const float* gat_W    = (const float*)d_in[4];
    const float* att_src  = (const float*)d_in[5];
    const float* att_dst  = (const float*)d_in[6];
    const float* gat_bias = (const float*)d_in[7];
    const float* Wih      = (const float*)d_in[8];
    const float* Whh      = (const float*)d_in[9];
    const float* bih      = (const float*)d_in[10];
    const float* bhh      = (const float*)d_in[11];
    const float* W1       = (const float*)d_in[12];
    const float* b1       = (const float*)d_in[13];
    const float* W2       = (const float*)d_in[14];
    const float* b2       = (const float*)d_in[15];
    float*       out      = (float*)d_out;

    const int* src = ei;
    const int* dst = ei + NEDGES;

    float* hA = nullptr;
    float* hB = nullptr;
    cudaGetSymbolAddress((void**)&hA, g_hA);
    cudaGetSymbolAddress((void**)&hB, g_hB);

    const int warpBlocks = (NNODES * 32 + 255) / 256;
    const int aggBlocks = (NNODES + 3) / 4;
    dim3 gg(NPAD / 128, 2);

    // order chosen so launch #4 is k_gemm_att (ncu fixed-window profiling)
    k_init_h<<<(NPAD * (DIM / 4) + 255) / 256, 256>>>(x);
    k_cvtW<<<(DIM * 2 * DIM + 255) / 256, 256>>>(gat_W);
    k_hist<<<(NEDGES + 255) / 256, 256>>>(dst);
    k_gemm_att<<<gg, 256>>>(att_src, att_dst);            // conv0 GEMM
    k_scan1<<<NCHUNK, 256>>>();
    k_scan2<<<1, 256>>>();
    k_scan3<<<NCHUNK, 256>>>();
    k_scatter<<<(ETOT + 255) / 256, 256>>>(src, dst);
    k_bptr<<<1, 256>>>(batch);
    k_zero_s2s<<<(BATCH * 512 + 255) / 256, 256>>>();

    float* cur = hA;
    float* nxt = hB;
    for (int c = 0; c < 3; c++) {
        if (c > 0) k_gemm_att<<<gg, 256>>>(att_src, att_dst);
        k_aggregate<<<aggBlocks, 256>>>(gat_bias, nxt);
        float* t = cur; cur = nxt; nxt = t;
    }

    for (int s = 0; s < 3; s++) {
        k_lstm<<<BATCH, 512>>>(Wih, Whh, bih, bhh);
        k_e<<<warpBlocks, 256>>>(cur, batch);
        k_segstat<<<BATCH, 256>>>();
        dim3 rg(BATCH, RCH);
        k_rpart<<<rg, 128>>>(cur);
        k_rred<<<BATCH, 128>>>();
    }

    k_mlp<<<BATCH, 128>>>(W1, b1, W2, b2, out);
}